// round 11
// baseline (speedup 1.0000x reference)
#include <cuda_runtime.h>
#include <math.h>
#include <stdint.h>

#define T_SEQ 4096
#define BATCH 2
#define CDIM  1024
#define HD    256
#define NH    4
#define WIN   512

// ---------------- scratch (static device globals; no allocation) ----------------
__device__ float    g_q [(size_t)BATCH * T_SEQ * CDIM];
__device__ float    g_k [(size_t)BATCH * T_SEQ * HD];
__device__ float    g_v [(size_t)BATCH * T_SEQ * HD];
__device__ float    g_ao[(size_t)BATCH * T_SEQ * CDIM];
__device__ float    g_invf[HD / 2];
// int8 two-digit operands (packed 4 s8 per u32), K = 1024 -> 256 u32/row
__device__ uint32_t g_x1 [(size_t)BATCH * T_SEQ * CDIM / 4];
__device__ uint32_t g_x2 [(size_t)BATCH * T_SEQ * CDIM / 4];
__device__ uint32_t g_ao1[(size_t)BATCH * T_SEQ * CDIM / 4];
__device__ uint32_t g_ao2[(size_t)BATCH * T_SEQ * CDIM / 4];
__device__ uint32_t g_wq1[CDIM * CDIM / 4];
__device__ uint32_t g_wq2[CDIM * CDIM / 4];
__device__ uint32_t g_wk1[HD * CDIM / 4];
__device__ uint32_t g_wk2[HD * CDIM / 4];
__device__ uint32_t g_wv1[HD * CDIM / 4];
__device__ uint32_t g_wv2[HD * CDIM / 4];
__device__ uint32_t g_wo1[CDIM * CDIM / 4];
__device__ uint32_t g_wo2[CDIM * CDIM / 4];
__device__ float    g_sx [BATCH * T_SEQ];
__device__ float    g_sao[BATCH * T_SEQ];
__device__ float    g_swq[CDIM];
__device__ float    g_swk[HD];
__device__ float    g_swv[HD];
__device__ float    g_swo[CDIM];
// pre-split bf16 attention operands
__device__ uint32_t g_qph[(size_t)BATCH * T_SEQ * CDIM / 2];
__device__ uint32_t g_qpl[(size_t)BATCH * T_SEQ * CDIM / 2];
__device__ uint32_t g_kph[(size_t)BATCH * T_SEQ * HD / 2];
__device__ uint32_t g_kpl[(size_t)BATCH * T_SEQ * HD / 2];
__device__ uint32_t g_vth[(size_t)BATCH * HD * T_SEQ / 2];
__device__ uint32_t g_vtl[(size_t)BATCH * HD * T_SEQ / 2];

// ---------------- RoPE inv_freq table ----------------
__global__ void init_invf()
{
    int i = threadIdx.x;
    float e = (float)(2 * i) * (1.0f / HD);
    g_invf[i] = (float)pow(1000000.0, -(double)e);
}

// ---------------- common helpers ----------------
__device__ __forceinline__ void split_bf16(float x, uint16_t& h, uint16_t& l) {
    asm("cvt.rn.bf16.f32 %0, %1;" : "=h"(h) : "f"(x));
    float r = x - __uint_as_float((uint32_t)h << 16);
    asm("cvt.rn.bf16.f32 %0, %1;" : "=h"(l) : "f"(r));
}
__device__ __forceinline__ uint32_t pack2(uint16_t a, uint16_t b) {
    return (uint32_t)a | ((uint32_t)b << 16);
}
__device__ __forceinline__ uint32_t smem_u32p(const void* p) {
    uint32_t a;
    asm("{ .reg .u64 t; cvta.to.shared.u64 t, %1; cvt.u32.u64 %0, t; }" : "=r"(a) : "l"(p));
    return a;
}

#define MMA_BF16(d, a, b) \
    asm volatile("mma.sync.aligned.m16n8k16.row.col.f32.bf16.bf16.f32 " \
        "{%0,%1,%2,%3}, {%4,%5,%6,%7}, {%8,%9}, {%0,%1,%2,%3};" \
        : "+f"((d)[0]), "+f"((d)[1]), "+f"((d)[2]), "+f"((d)[3]) \
        : "r"((a)[0]), "r"((a)[1]), "r"((a)[2]), "r"((a)[3]), \
          "r"((b)[0]), "r"((b)[1]))

#define MMA_S8(d, a, b) \
    asm volatile("mma.sync.aligned.m16n8k32.row.col.s32.s8.s8.s32 " \
        "{%0,%1,%2,%3}, {%4,%5,%6,%7}, {%8,%9}, {%0,%1,%2,%3};" \
        : "+r"((d)[0]), "+r"((d)[1]), "+r"((d)[2]), "+r"((d)[3]) \
        : "r"((a)[0]), "r"((a)[1]), "r"((a)[2]), "r"((a)[3]), \
          "r"((b)[0]), "r"((b)[1]))

#define LDSM4(r0, r1, r2, r3, a) \
    asm volatile("ldmatrix.sync.aligned.m8n8.x4.shared.b16 {%0,%1,%2,%3}, [%4];" \
        : "=r"(r0), "=r"(r1), "=r"(r2), "=r"(r3) : "r"(a))

__device__ __forceinline__ void cpa16(uint32_t sa, const void* ga) {
    asm volatile("cp.async.cg.shared.global [%0], [%1], 16;" :: "r"(sa), "l"(ga));
}
#define CP_COMMIT() asm volatile("cp.async.commit_group;" ::: "memory")
#define CP_WAIT0()  asm volatile("cp.async.wait_group 0;" ::: "memory")
#define CP_WAIT1()  asm volatile("cp.async.wait_group 1;" ::: "memory")

// ---------------- fp32 rows -> two int8 digits + per-row scale (K=1024) --------
__global__ __launch_bounds__(256) void quant_rows(
    const float* __restrict__ in, uint32_t* __restrict__ d1, uint32_t* __restrict__ d2,
    float* __restrict__ s, int rows)
{
    int warp = (int)((blockIdx.x * blockDim.x + threadIdx.x) >> 5);
    int lane = threadIdx.x & 31;
    if (warp >= rows) return;
    const float* row = in + (size_t)warp * CDIM;

    float4 v[8];
    float vmax = 1e-20f;
#pragma unroll
    for (int i = 0; i < 8; i++) {
        v[i] = *(const float4*)(row + (lane + i * 32) * 4);
        vmax = fmaxf(vmax, fmaxf(fmaxf(fabsf(v[i].x), fabsf(v[i].y)),
                                 fmaxf(fabsf(v[i].z), fabsf(v[i].w))));
    }
#pragma unroll
    for (int o = 16; o > 0; o >>= 1)
        vmax = fmaxf(vmax, __shfl_xor_sync(0xffffffffu, vmax, o));

    float sa  = vmax * (1.0f / 127.0f);
    float inv = 127.0f / vmax;
    if (lane == 0) s[warp] = sa;

    uint32_t* p1 = d1 + (size_t)warp * (CDIM / 4);
    uint32_t* p2 = d2 + (size_t)warp * (CDIM / 4);
#pragma unroll
    for (int i = 0; i < 8; i++) {
        const float* f = (const float*)&v[i];
        uint32_t u1 = 0, u2 = 0;
#pragma unroll
        for (int j = 0; j < 4; j++) {
            float t = f[j] * inv;
            int q1 = __float2int_rn(t);
            float r = t - (float)q1;
            int q2 = __float2int_rn(r * 256.0f);
            q2 = max(-127, min(127, q2));
            u1 |= ((uint32_t)q1 & 0xffu) << (j * 8);
            u2 |= ((uint32_t)q2 & 0xffu) << (j * 8);
        }
        p1[lane + i * 32] = u1;
        p2[lane + i * 32] = u2;
    }
}

// ============ int8 two-digit GEMM: C = sa·sb·(A1B1 + (A1B2+A2B1)/256) ============
// CTA tile 128x128, BK=64 int8 (2 k32 steps), 3-stage cp.async, K fixed 1024.
#define STRP 20                               // u32/row: 16 data + 4 pad
#define PART_U32 (128 * STRP)                 // 2560
#define BUF_U32  (4 * PART_U32)               // A1,A2,B1,B2
#define GEMM_SMEM (3 * BUF_U32 * 4)           // 122880 B
#define K4 256                                // u32 per row (K=1024 s8)
#define NT 16

__global__ __launch_bounds__(256, 1) void gemm_s8(
    int M, int tiles0, int tiles01,
    const uint32_t* __restrict__ A1, const uint32_t* __restrict__ A2, const float* __restrict__ sA,
    const uint32_t* __restrict__ B1_0, const uint32_t* __restrict__ B2_0, const float* __restrict__ sB_0, float* __restrict__ C_0, int N_0,
    const uint32_t* __restrict__ B1_1, const uint32_t* __restrict__ B2_1, const float* __restrict__ sB_1, float* __restrict__ C_1, int N_1,
    const uint32_t* __restrict__ B1_2, const uint32_t* __restrict__ B2_2, const float* __restrict__ sB_2, float* __restrict__ C_2, int N_2)
{
    extern __shared__ uint32_t s32[];
    const uint32_t sb_ = smem_u32p(s32);

    const int nt = blockIdx.x;
    const uint32_t *B1, *B2; const float* sB; float* C; int N, ntl;
    if (nt < tiles0)       { B1 = B1_0; B2 = B2_0; sB = sB_0; C = C_0; N = N_0; ntl = nt; }
    else if (nt < tiles01) { B1 = B1_1; B2 = B2_1; sB = sB_1; C = C_1; N = N_1; ntl = nt - tiles0; }
    else                   { B1 = B1_2; B2 = B2_2; sB = sB_2; C = C_2; N = N_2; ntl = nt - tiles01; }

    const int tid    = threadIdx.x;
    const int wid    = tid >> 5;
    const int lane   = tid & 31;
    const int quad   = lane >> 2;
    const int tq     = lane & 3;
    const int warp_m = wid & 3;
    const int warp_n = wid >> 2;
    const int m0 = blockIdx.y << 7;
    const int n0 = ntl << 7;

    const int jm   = lane >> 3, jr = lane & 7;
    const int a_ro = (jm & 1) * 8 + jr;
    const int a_ko = (jm >> 1) * 4;
    const int b_go = jm >> 1;
    const int b_ko = (jm & 1) * 4;

    const uint32_t* pA1 = A1 + (size_t)m0 * K4;
    const uint32_t* pA2 = A2 + (size_t)m0 * K4;
    const uint32_t* pB1 = B1 + (size_t)n0 * K4;
    const uint32_t* pB2 = B2 + (size_t)n0 * K4;

    const int r_  = tid >> 1;            // 0..127
    const int qd0 = (tid & 1) * 8;       // u32 col of first 16B chunk

#define LOADP(it, buf) do { \
    int kp = (it) * 16; \
    uint32_t sbase = sb_ + (uint32_t)(buf) * BUF_U32 * 4u; \
    cpa16(sbase + (uint32_t)(0*PART_U32 + r_*STRP + qd0    )*4u, pA1 + (size_t)r_*K4 + kp + qd0); \
    cpa16(sbase + (uint32_t)(0*PART_U32 + r_*STRP + qd0 + 4)*4u, pA1 + (size_t)r_*K4 + kp + qd0 + 4); \
    cpa16(sbase + (uint32_t)(1*PART_U32 + r_*STRP + qd0    )*4u, pA2 + (size_t)r_*K4 + kp + qd0); \
    cpa16(sbase + (uint32_t)(1*PART_U32 + r_*STRP + qd0 + 4)*4u, pA2 + (size_t)r_*K4 + kp + qd0 + 4); \
    cpa16(sbase + (uint32_t)(2*PART_U32 + r_*STRP + qd0    )*4u, pB1 + (size_t)r_*K4 + kp + qd0); \
    cpa16(sbase + (uint32_t)(2*PART_U32 + r_*STRP + qd0 + 4)*4u, pB1 + (size_t)r_*K4 + kp + qd0 + 4); \
    cpa16(sbase + (uint32_t)(3*PART_U32 + r_*STRP + qd0    )*4u, pB2 + (size_t)r_*K4 + kp + qd0); \
    cpa16(sbase + (uint32_t)(3*PART_U32 + r_*STRP + qd0 + 4)*4u, pB2 + (size_t)r_*K4 + kp + qd0 + 4); \
    CP_COMMIT(); \
} while (0)

    int acc_hi[2][8][4], acc_lo[2][8][4];
#pragma unroll
    for (int mf = 0; mf < 2; mf++)
#pragma unroll
        for (int nf = 0; nf < 8; nf++)
#pragma unroll
            for (int r = 0; r < 4; r++) { acc_hi[mf][nf][r] = 0; acc_lo[mf][nf][r] = 0; }

    LOADP(0, 0);
    LOADP(1, 1);

    for (int it = 0; it < NT; ++it) {
        if (it + 2 < NT) { CP_WAIT1(); } else { CP_WAIT0(); }
        __syncthreads();
        if (it + 2 < NT) LOADP(it + 2, (it + 2) % 3);

        const uint32_t sA = sb_ + (uint32_t)(it % 3) * BUF_U32 * 4u;
        const uint32_t sB = sA + 2u * PART_U32 * 4u;

#pragma unroll
        for (int ks = 0; ks < 2; ks++) {
            const int kb = ks * 8;
            uint32_t a1[2][4], a2[2][4];
#pragma unroll
            for (int mf = 0; mf < 2; mf++) {
                uint32_t ar = sA + (uint32_t)((warp_m*32 + mf*16 + a_ro) * STRP + kb + a_ko) * 4u;
                LDSM4(a1[mf][0], a1[mf][1], a1[mf][2], a1[mf][3], ar);
                LDSM4(a2[mf][0], a2[mf][1], a2[mf][2], a2[mf][3], ar + PART_U32*4u);
            }
#pragma unroll
            for (int g = 0; g < 4; g++) {
                uint32_t br = sB + (uint32_t)((warp_n*64 + (2*g + b_go)*8 + jr) * STRP + kb + b_ko) * 4u;
                uint32_t b01[2], b11[2], b02[2], b12[2];
                LDSM4(b01[0], b01[1], b11[0], b11[1], br);
                LDSM4(b02[0], b02[1], b12[0], b12[1], br + PART_U32*4u);
#pragma unroll
                for (int mf = 0; mf < 2; mf++) {
                    MMA_S8(acc_hi[mf][2*g],   a1[mf], b01);
                    MMA_S8(acc_lo[mf][2*g],   a1[mf], b02);
                    MMA_S8(acc_lo[mf][2*g],   a2[mf], b01);
                    MMA_S8(acc_hi[mf][2*g+1], a1[mf], b11);
                    MMA_S8(acc_lo[mf][2*g+1], a1[mf], b12);
                    MMA_S8(acc_lo[mf][2*g+1], a2[mf], b11);
                }
            }
        }
    }

    // epilogue: c = sa_row * sb_col * (hi + lo/256); sB indexed by SEGMENT-GLOBAL col
    float sav[2][2];
#pragma unroll
    for (int mf = 0; mf < 2; mf++) {
        sav[mf][0] = sA[m0 + warp_m * 32 + mf * 16 + quad];
        sav[mf][1] = sA[m0 + warp_m * 32 + mf * 16 + quad + 8];
    }
#pragma unroll
    for (int mf = 0; mf < 2; mf++) {
        int row = m0 + warp_m * 32 + mf * 16 + quad;
#pragma unroll
        for (int nf = 0; nf < 8; nf++) {
            int col = n0 + warp_n * 64 + nf * 8 + tq * 2;
            float sc0 = sB[col];
            float sc1 = sB[col + 1];
            float v00 = sav[mf][0] * sc0 * ((float)acc_hi[mf][nf][0] + (float)acc_lo[mf][nf][0] * (1.0f/256.0f));
            float v01 = sav[mf][0] * sc1 * ((float)acc_hi[mf][nf][1] + (float)acc_lo[mf][nf][1] * (1.0f/256.0f));
            float v10 = sav[mf][1] * sc0 * ((float)acc_hi[mf][nf][2] + (float)acc_lo[mf][nf][2] * (1.0f/256.0f));
            float v11 = sav[mf][1] * sc1 * ((float)acc_hi[mf][nf][3] + (float)acc_lo[mf][nf][3] * (1.0f/256.0f));
            *(float2*)(C + (size_t)row * N + col)       = make_float2(v00, v01);
            *(float2*)(C + (size_t)(row + 8) * N + col) = make_float2(v10, v11);
        }
    }
#undef LOADP
}

// ---------------- fused RMSNorm + RoPE -> packed bf16x2 hi/lo ----------------
__global__ void rmsnorm_rope_pack(const float* __restrict__ in, const float* __restrict__ gamma,
                                  uint32_t* __restrict__ oh, uint32_t* __restrict__ ol,
                                  int nrows, int heads)
{
    int gw   = (int)((blockIdx.x * blockDim.x + threadIdx.x) >> 5);
    int lane = threadIdx.x & 31;
    if (gw >= nrows) return;
    int bt = gw / heads;
    int t  = bt & (T_SEQ - 1);

    const float* row = in + (size_t)gw * HD;

    float v[8];
    *(float4*)&v[0] = *(const float4*)(row + lane * 8);
    *(float4*)&v[4] = *(const float4*)(row + lane * 8 + 4);

    float ss = 0.f;
#pragma unroll
    for (int i = 0; i < 8; i++) ss += v[i] * v[i];
#pragma unroll
    for (int o = 16; o > 0; o >>= 1) ss += __shfl_xor_sync(0xffffffffu, ss, o);

    float r = rsqrtf(ss * (1.0f / HD) + 1e-6f);

    float g[8];
    *(float4*)&g[0] = *(const float4*)(gamma + lane * 8);
    *(float4*)&g[4] = *(const float4*)(gamma + lane * 8 + 4);

    float invf[4];
    *(float4*)invf = *(const float4*)(g_invf + lane * 4);

    float tf = (float)t;
#pragma unroll
    for (int p = 0; p < 4; p++) {
        float ang = tf * invf[p];
        float c, s;
        sincosf(ang, &s, &c);
        float x0 = v[2 * p]     * r * g[2 * p];
        float x1 = v[2 * p + 1] * r * g[2 * p + 1];
        v[2 * p]     = x0 * c - x1 * s;
        v[2 * p + 1] = x0 * s + x1 * c;
    }

    uint16_t hh[8], ll[8];
#pragma unroll
    for (int i = 0; i < 8; i++) split_bf16(v[i], hh[i], ll[i]);
    size_t ob = (size_t)gw * (HD / 2) + lane * 4;
    *(uint4*)(oh + ob) = make_uint4(pack2(hh[0],hh[1]), pack2(hh[2],hh[3]),
                                    pack2(hh[4],hh[5]), pack2(hh[6],hh[7]));
    *(uint4*)(ol + ob) = make_uint4(pack2(ll[0],ll[1]), pack2(ll[2],ll[3]),
                                    pack2(ll[4],ll[5]), pack2(ll[6],ll[7]));
}

// ---------------- V transpose + split ----------------
#define VT_SMEM (256 * 69 * 4)
__global__ __launch_bounds__(256) void transpose_split_v(
    const float* __restrict__ v, uint32_t* __restrict__ vth, uint32_t* __restrict__ vtl)
{
    extern __shared__ float st[];
    int b = blockIdx.y, t0 = blockIdx.x * 64;
    int tid = threadIdx.x;
    const float* vb = v + ((size_t)(b * T_SEQ + t0)) * HD;
#pragma unroll
    for (int i = 0; i < 16; i++) {
        int f = i * 256 + tid;
        int t = f >> 6, d4 = (f & 63) * 4;
        float4 x = *(const float4*)(vb + (size_t)t * HD + d4);
        st[(d4 + 0) * 69 + t] = x.x;
        st[(d4 + 1) * 69 + t] = x.y;
        st[(d4 + 2) * 69 + t] = x.z;
        st[(d4 + 3) * 69 + t] = x.w;
    }
    __syncthreads();
    int w = tid >> 5, l = tid & 31;
#pragma unroll
    for (int pass = 0; pass < 32; pass++) {
        int d = pass * 8 + w;
        float x0 = st[d * 69 + 2 * l];
        float x1 = st[d * 69 + 2 * l + 1];
        uint16_t h0, l0, h1, l1;
        split_bf16(x0, h0, l0); split_bf16(x1, h1, l1);
        size_t o = ((size_t)(b * HD + d)) * (T_SEQ / 2) + (t0 >> 1) + l;
        vth[o] = pack2(h0, h1);
        vtl[o] = pack2(l0, l1);
    }
}

// =========== sliding-window flash attention (bf16 3-term, unchanged) ===========
#define AQ_STR 132
#define AV_STR 36
#define OFF_QH   0
#define OFF_QL   (64 * AQ_STR)
#define OFF_KVH  (2 * 64 * AQ_STR)
#define OFF_KVL  (OFF_KVH + 9216)
#define OFF_PH   (OFF_KVL + 9216)
#define OFF_PL   (OFF_PH + 64 * AV_STR)
#define OFF_RED  (OFF_PL + 64 * AV_STR)
#define OFF_RED2 (OFF_RED + 256)
#define OFF_MS   (OFF_RED2 + 256)
#define OFF_LS   (OFF_MS + 64)
#define ATTN_U32 (OFF_LS + 64)
#define ATTN_SMEM (ATTN_U32 * 4)

__global__ __launch_bounds__(256, 1) void attn_swa_mma(
    const uint32_t* __restrict__ Qph, const uint32_t* __restrict__ Qpl,
    const uint32_t* __restrict__ Kph, const uint32_t* __restrict__ Kpl,
    const uint32_t* __restrict__ Vth, const uint32_t* __restrict__ Vtl,
    float* __restrict__ AO)
{
    extern __shared__ uint32_t s[];
    const uint32_t sb = smem_u32p(s);
    uint32_t* Ph   = s + OFF_PH;
    uint32_t* Pl   = s + OFF_PL;
    float* red     = (float*)(s + OFF_RED);
    float* red2    = (float*)(s + OFF_RED2);
    float* m_s     = (float*)(s + OFF_MS);
    float* l_s     = (float*)(s + OFF_LS);

    const int tid  = threadIdx.x;
    const int wid  = tid >> 5, lane = tid & 31, quad = lane >> 2, tq = lane & 3;
    const int wm   = wid & 1, wn = wid >> 1;
    const int jm   = lane >> 3, jr = lane & 7;
    const int a_ro = (jm & 1) * 8 + jr;
    const int a_ko = (jm >> 1) * 4;
    const int b_go = jm >> 1;
    const int b_ko = (jm & 1) * 4;
    const int qt   = blockIdx.x & 63;
    const int h    = (blockIdx.x >> 6) & 3;
    const int b    = blockIdx.x >> 8;
    const int q0   = qt << 6;

    const uint32_t* qh_g = Qph + ((size_t)(b * T_SEQ + q0)) * (CDIM / 2) + h * (HD / 2);
    const uint32_t* ql_g = Qpl + ((size_t)(b * T_SEQ + q0)) * (CDIM / 2) + h * (HD / 2);
    const uint32_t* kh_g = Kph + (size_t)b * T_SEQ * (HD / 2);
    const uint32_t* kl_g = Kpl + (size_t)b * T_SEQ * (HD / 2);
    const uint32_t* vh_g = Vth + (size_t)b * HD * (T_SEQ / 2);
    const uint32_t* vl_g = Vtl + (size_t)b * HD * (T_SEQ / 2);

#pragma unroll
    for (int i = 0; i < 8; i++) {
        int f = i * 256 + tid, row = f >> 5, c4 = (f & 31) * 4;
        cpa16(sb + (uint32_t)(OFF_QH + row * AQ_STR + c4) * 4u, qh_g + (size_t)row * (CDIM / 2) + c4);
        cpa16(sb + (uint32_t)(OFF_QL + row * AQ_STR + c4) * 4u, ql_g + (size_t)row * (CDIM / 2) + c4);
    }
    CP_COMMIT();
    if (tid < 64) { m_s[tid] = -1e30f; l_s[tid] = 0.f; }
    CP_WAIT0();
    __syncthreads();

    float oacc[2][8][4];
#pragma unroll
    for (int mf = 0; mf < 2; mf++)
#pragma unroll
        for (int nf = 0; nf < 8; nf++)
#pragma unroll
            for (int r = 0; r < 4; r++) oacc[mf][nf][r] = 0.f;

    int kt0 = q0 - WIN; if (kt0 < 0) kt0 = 0;

    for (int kt = kt0; kt <= q0; kt += 64) {
        __syncthreads();   // A

#pragma unroll
        for (int i = 0; i < 8; i++) {
            int f = i * 256 + tid, row = f >> 5, c4 = (f & 31) * 4;
            cpa16(sb + (uint32_t)(OFF_KVH + row * AQ_STR + c4) * 4u, kh_g + (size_t)(kt + row) * (HD / 2) + c4);
            cpa16(sb + (uint32_t)(OFF_KVL + row * AQ_STR + c4) * 4u, kl_g + (size_t)(kt + row) * (HD / 2) + c4);
        }
        CP_COMMIT();
        CP_WAIT0();
        __syncthreads();   // B

        float sacc[2][2][4];
#pragma unroll
        for (int mf = 0; mf < 2; mf++)
#pragma unroll
            for (int nf = 0; nf < 2; nf++)
#pragma unroll
                for (int r = 0; r < 4; r++) sacc[mf][nf][r] = 0.f;

#pragma unroll
        for (int ks = 0; ks < 16; ks++) {
            const int kb = ks * 8;
            uint32_t ah[2][4], al[2][4];
#pragma unroll
            for (int mf = 0; mf < 2; mf++) {
                uint32_t ar = sb + (uint32_t)(OFF_QH + (wm*32 + mf*16 + a_ro) * AQ_STR + kb + a_ko) * 4u;
                LDSM4(ah[mf][0], ah[mf][1], ah[mf][2], ah[mf][3], ar);
                LDSM4(al[mf][0], al[mf][1], al[mf][2], al[mf][3], ar + (OFF_QL - OFF_QH) * 4u);
            }
            uint32_t br = sb + (uint32_t)(OFF_KVH + (wn*16 + b_go*8 + jr) * AQ_STR + kb + b_ko) * 4u;
            uint32_t b0h[2], b1h[2], b0l[2], b1l[2];
            LDSM4(b0h[0], b0h[1], b1h[0], b1h[1], br);
            LDSM4(b0l[0], b0l[1], b1l[0], b1l[1], br + (OFF_KVL - OFF_KVH) * 4u);
#pragma unroll
            for (int mf = 0; mf < 2; mf++) {
                MMA_BF16(sacc[mf][0], ah[mf], b0h);
                MMA_BF16(sacc[mf][0], ah[mf], b0l);
                MMA_BF16(sacc[mf][0], al[mf], b0h);
                MMA_BF16(sacc[mf][1], ah[mf], b1h);
                MMA_BF16(sacc[mf][1], ah[mf], b1l);
                MMA_BF16(sacc[mf][1], al[mf], b1h);
            }
        }

#pragma unroll
        for (int mf = 0; mf < 2; mf++)
#pragma unroll
            for (int half = 0; half < 2; half++) {
                int rowl = wm * 32 + mf * 16 + quad + half * 8;
                int irow = q0 + rowl;
                float mt = -1e30f;
#pragma unroll
                for (int nf = 0; nf < 2; nf++)
#pragma unroll
                    for (int p = 0; p < 2; p++) {
                        int j = kt + wn * 16 + nf * 8 + tq * 2 + p;
                        bool ok = (j <= irow) && (j >= irow - WIN);
                        float x = ok ? sacc[mf][nf][half * 2 + p] * 0.0625f : -1e30f;
                        sacc[mf][nf][half * 2 + p] = x;
                        mt = fmaxf(mt, x);
                    }
                mt = fmaxf(mt, __shfl_xor_sync(0xffffffffu, mt, 1));
                mt = fmaxf(mt, __shfl_xor_sync(0xffffffffu, mt, 2));
                if (tq == 0) red[wn * 64 + rowl] = mt;
            }
        __syncthreads();   // C

#pragma unroll
        for (int i = 0; i < 8; i++) {
            int f = i * 256 + tid, d = f >> 3, c4 = (f & 7) * 4;
            cpa16(sb + (uint32_t)(OFF_KVH + d * AV_STR + c4) * 4u, vh_g + (size_t)d * (T_SEQ / 2) + (kt >> 1) + c4);
            cpa16(sb + (uint32_t)(OFF_KVL + d * AV_STR + c4) * 4u, vl_g + (size_t)d * (T_SEQ / 2) + (kt >> 1) + c4);
        }
        CP_COMMIT();

        float mn_loc[2][2], corr_loc[2][2];
#pragma unroll
        for (int mf = 0; mf < 2; mf++)
#pragma unroll
            for (int half = 0; half < 2; half++) {
                int rowl = wm * 32 + mf * 16 + quad + half * 8;
                float mt = fmaxf(fmaxf(red[rowl], red[64 + rowl]),
                                 fmaxf(red[128 + rowl], red[192 + rowl]));
                float mo = m_s[rowl];
                float mn = fmaxf(mo, mt);
                mn_loc[mf][half]   = mn;
                corr_loc[mf][half] = __expf(mo - mn);
            }

#pragma unroll
        for (int mf = 0; mf < 2; mf++)
#pragma unroll
            for (int half = 0; half < 2; half++) {
                int rowl = wm * 32 + mf * 16 + quad + half * 8;
                float mn = mn_loc[mf][half];
                float rs = 0.f;
#pragma unroll
                for (int nf = 0; nf < 2; nf++) {
                    float p0 = __expf(sacc[mf][nf][half * 2 + 0] - mn);
                    float p1 = __expf(sacc[mf][nf][half * 2 + 1] - mn);
                    rs += p0 + p1;
                    uint16_t h0, l0, h1, l1;
                    split_bf16(p0, h0, l0); split_bf16(p1, h1, l1);
                    int o = rowl * AV_STR + wn * 8 + nf * 4 + tq;
                    Ph[o] = pack2(h0, h1);
                    Pl[o] = pack2(l0, l1);
                }
                rs += __shfl_xor_sync(0xffffffffu, rs, 1);
                rs += __shfl_xor_sync(0xffffffffu, rs, 2);
                if (tq == 0) red2[wn * 64 + rowl] = rs;
            }
        __syncthreads();   // E

        if (wid < 2 && tq == 0) {
#pragma unroll
            for (int mf = 0; mf < 2; mf++)
#pragma unroll
                for (int half = 0; half < 2; half++) {
                    int rowl = wid * 32 + mf * 16 + quad + half * 8;
                    l_s[rowl] = l_s[rowl] * corr_loc[mf][half] +
                                red2[rowl] + red2[64 + rowl] + red2[128 + rowl] + red2[192 + rowl];
                    m_s[rowl] = mn_loc[mf][half];
                }
        }
#pragma unroll
        for (int mf = 0; mf < 2; mf++) {
            float c0 = corr_loc[mf][0], c1 = corr_loc[mf][1];
#pragma unroll
            for (int nf = 0; nf < 8; nf++) {
                oacc[mf][nf][0] *= c0; oacc[mf][nf][1] *= c0;
                oacc[mf][nf][2] *= c1; oacc[mf][nf][3] *= c1;
            }
        }
        CP_WAIT0();
        __syncthreads();   // F

#pragma unroll
        for (int kk = 0; kk < 4; kk++) {
            const int kb = kk * 8;
            uint32_t pah[2][4], pal[2][4];
#pragma unroll
            for (int mf = 0; mf < 2; mf++) {
                uint32_t ar = sb + (uint32_t)(OFF_PH + (wm*32 + mf*16 + a_ro) * AV_STR + kb + a_ko) * 4u;
                LDSM4(pah[mf][0], pah[mf][1], pah[mf][2], pah[mf][3], ar);
                LDSM4(pal[mf][0], pal[mf][1], pal[mf][2], pal[mf][3], ar + (OFF_PL - OFF_PH) * 4u);
            }
#pragma unroll
            for (int g = 0; g < 4; g++) {
                uint32_t br = sb + (uint32_t)(OFF_KVH + (wn*64 + (2*g + b_go)*8 + jr) * AV_STR + kb + b_ko) * 4u;
                uint32_t v0h[2], v1h[2], v0l[2], v1l[2];
                LDSM4(v0h[0], v0h[1], v1h[0], v1h[1], br);
                LDSM4(v0l[0], v0l[1], v1l[0], v1l[1], br + (OFF_KVL - OFF_KVH) * 4u);
#pragma unroll
                for (int mf = 0; mf < 2; mf++) {
                    MMA_BF16(oacc[mf][2*g],   pah[mf], v0h);
                    MMA_BF16(oacc[mf][2*g],   pah[mf], v0l);
                    MMA_BF16(oacc[mf][2*g],   pal[mf], v0h);
                    MMA_BF16(oacc[mf][2*g+1], pah[mf], v1h);
                    MMA_BF16(oacc[mf][2*g+1], pah[mf], v1l);
                    MMA_BF16(oacc[mf][2*g+1], pal[mf], v1h);
                }
            }
        }
    }

    // epilogue: fp32 ao
#pragma unroll
    for (int mf = 0; mf < 2; mf++) {
        int r0 = wm * 32 + mf * 16 + quad;
        float i0 = 1.f / l_s[r0], i1 = 1.f / l_s[r0 + 8];
        float* ob = AO + ((size_t)(b * T_SEQ + q0 + r0)) * CDIM + (size_t)h * HD;
#pragma unroll
        for (int nf = 0; nf < 8; nf++) {
            int col = wn * 64 + nf * 8 + tq * 2;
            *(float2*)(ob + col)            = make_float2(oacc[mf][nf][0] * i0, oacc[mf][nf][1] * i0);
            *(float2*)(ob + 8 * CDIM + col) = make_float2(oacc[mf][nf][2] * i1, oacc[mf][nf][3] * i1);
        }
    }
}

// ---------------- launch ----------------
extern "C" void kernel_launch(void* const* d_in, const int* in_sizes, int n_in,
                              void* d_out, int out_size)
{
    const float* x  = (const float*)d_in[0];
    const float* Wq = (const float*)d_in[1];
    const float* Wk = (const float*)d_in[2];
    const float* Wv = (const float*)d_in[3];
    const float* Wo = (const float*)d_in[4];
    const float* qg = (const float*)d_in[5];
    const float* kg = (const float*)d_in[6];
    float* out = (float*)d_out;

    float *q, *k, *v, *ao;
    uint32_t *x1, *x2, *ao1, *ao2, *wq1, *wq2, *wk1, *wk2, *wv1, *wv2, *wo1, *wo2;
    float *sx, *sao, *swq, *swk, *swv, *swo;
    uint32_t *qph, *qpl, *kph, *kpl, *vth, *vtl;
    cudaGetSymbolAddress((void**)&q,   g_q);
    cudaGetSymbolAddress((void**)&k,   g_k);
    cudaGetSymbolAddress((void**)&v,   g_v);
    cudaGetSymbolAddress((void**)&ao,  g_ao);
    cudaGetSymbolAddress((void**)&x1,  g_x1);
    cudaGetSymbolAddress((void**)&x2,  g_x2);
    cudaGetSymbolAddress((void**)&ao1, g_ao1);
    cudaGetSymbolAddress((void**)&ao2, g_ao2);
    cudaGetSymbolAddress((void**)&wq1, g_wq1);
    cudaGetSymbolAddress((void**)&wq2, g_wq2);
    cudaGetSymbolAddress((void**)&wk1, g_wk1);
    cudaGetSymbolAddress((void**)&wk2, g_wk2);
    cudaGetSymbolAddress((void**)&wv1, g_wv1);
    cudaGetSymbolAddress((void**)&wv2, g_wv2);
    cudaGetSymbolAddress((void**)&wo1, g_wo1);
    cudaGetSymbolAddress((void**)&wo2, g_wo2);
    cudaGetSymbolAddress((void**)&sx,  g_sx);
    cudaGetSymbolAddress((void**)&sao, g_sao);
    cudaGetSymbolAddress((void**)&swq, g_swq);
    cudaGetSymbolAddress((void**)&swk, g_swk);
    cudaGetSymbolAddress((void**)&swv, g_swv);
    cudaGetSymbolAddress((void**)&swo, g_swo);
    cudaGetSymbolAddress((void**)&qph, g_qph);
    cudaGetSymbolAddress((void**)&qpl, g_qpl);
    cudaGetSymbolAddress((void**)&kph, g_kph);
    cudaGetSymbolAddress((void**)&kpl, g_kpl);
    cudaGetSymbolAddress((void**)&vth, g_vth);
    cudaGetSymbolAddress((void**)&vtl, g_vtl);

    const int M = BATCH * T_SEQ;   // 8192

    init_invf<<<1, 128>>>();

    quant_rows<<<M / 8, 256>>>(x,  x1,  x2,  sx,  M);
    quant_rows<<<CDIM / 8, 256>>>(Wq, wq1, wq2, swq, CDIM);
    quant_rows<<<HD / 8, 256>>>(Wk, wk1, wk2, swk, HD);
    quant_rows<<<HD / 8, 256>>>(Wv, wv1, wv2, swv, HD);
    quant_rows<<<CDIM / 8, 256>>>(Wo, wo1, wo2, swo, CDIM);

    cudaFuncSetAttribute(gemm_s8, cudaFuncAttributeMaxDynamicSharedMemorySize, GEMM_SMEM);

    // fused Q+K+V projection: n-tiles 0-7 -> Wq/q, 8-9 -> Wk/k, 10-11 -> Wv/v
    gemm_s8<<<dim3(12, M / 128), 256, GEMM_SMEM>>>(
        M, 8, 10, x1, x2, sx,
        wq1, wq2, swq, q, CDIM,
        wk1, wk2, swk, k, HD,
        wv1, wv2, swv, v, HD);

    rmsnorm_rope_pack<<<(M * NH) / 8, 256>>>(q, qg, qph, qpl, M * NH, NH);
    rmsnorm_rope_pack<<<M / 8, 256>>>(k, kg, kph, kpl, M, 1);

    cudaFuncSetAttribute(transpose_split_v, cudaFuncAttributeMaxDynamicSharedMemorySize, VT_SMEM);
    transpose_split_v<<<dim3(T_SEQ / 64, BATCH), 256, VT_SMEM>>>(v, vth, vtl);

    cudaFuncSetAttribute(attn_swa_mma, cudaFuncAttributeMaxDynamicSharedMemorySize, ATTN_SMEM);
    attn_swa_mma<<<BATCH * NH * (T_SEQ / 64), 256, ATTN_SMEM>>>(
        qph, qpl, kph, kpl, vth, vtl, ao);

    quant_rows<<<M / 8, 256>>>(ao, ao1, ao2, sao, M);

    // output projection
    gemm_s8<<<dim3(8, M / 128), 256, GEMM_SMEM>>>(
        M, 8, 8, ao1, ao2, sao,
        wo1, wo2, swo, out, CDIM,
        wo1, wo2, swo, out, CDIM,
        wo1, wo2, swo, out, CDIM);
}

// round 12
// speedup vs baseline: 2.5616x; 2.5616x over previous
#include <cuda_runtime.h>
#include <math.h>
#include <stdint.h>

#define T_SEQ 4096
#define BATCH 2
#define CDIM  1024
#define HD    256
#define NH    4
#define WIN   512

// ---------------- scratch (static device globals; no allocation) ----------------
__device__ float    g_q [(size_t)BATCH * T_SEQ * CDIM];
__device__ float    g_k [(size_t)BATCH * T_SEQ * HD];
__device__ float    g_v [(size_t)BATCH * T_SEQ * HD];
__device__ float    g_invf[HD / 2];
// packed f16x2 hi/lo operand buffers (GEMM)
__device__ uint32_t g_xh [(size_t)BATCH * T_SEQ * CDIM / 2];
__device__ uint32_t g_xl [(size_t)BATCH * T_SEQ * CDIM / 2];
__device__ uint32_t g_aoh[(size_t)BATCH * T_SEQ * CDIM / 2];
__device__ uint32_t g_aol[(size_t)BATCH * T_SEQ * CDIM / 2];
__device__ uint32_t g_wqh[CDIM * CDIM / 2];
__device__ uint32_t g_wql[CDIM * CDIM / 2];
__device__ uint32_t g_wkh[HD * CDIM / 2];
__device__ uint32_t g_wkl[HD * CDIM / 2];
__device__ uint32_t g_wvh[HD * CDIM / 2];
__device__ uint32_t g_wvl[HD * CDIM / 2];
__device__ uint32_t g_woh[CDIM * CDIM / 2];
__device__ uint32_t g_wol[CDIM * CDIM / 2];
// pre-split bf16 attention operands
__device__ uint32_t g_qph[(size_t)BATCH * T_SEQ * CDIM / 2];
__device__ uint32_t g_qpl[(size_t)BATCH * T_SEQ * CDIM / 2];
__device__ uint32_t g_kph[(size_t)BATCH * T_SEQ * HD / 2];
__device__ uint32_t g_kpl[(size_t)BATCH * T_SEQ * HD / 2];
__device__ uint32_t g_vth[(size_t)BATCH * HD * T_SEQ / 2];
__device__ uint32_t g_vtl[(size_t)BATCH * HD * T_SEQ / 2];

// ---------------- RoPE inv_freq table ----------------
__global__ void init_invf()
{
    int i = threadIdx.x;
    float e = (float)(2 * i) * (1.0f / HD);
    g_invf[i] = (float)pow(1000000.0, -(double)e);
}

// ---------------- common helpers ----------------
__device__ __forceinline__ void split_bf16(float x, uint16_t& h, uint16_t& l) {
    asm("cvt.rn.bf16.f32 %0, %1;" : "=h"(h) : "f"(x));
    float r = x - __uint_as_float((uint32_t)h << 16);
    asm("cvt.rn.bf16.f32 %0, %1;" : "=h"(l) : "f"(r));
}
__device__ __forceinline__ void split_f16(float x, uint16_t& h, uint16_t& l) {
    asm("cvt.rn.f16.f32 %0, %1;" : "=h"(h) : "f"(x));
    float hf;
    asm("cvt.f32.f16 %0, %1;" : "=f"(hf) : "h"(h));
    float r = x - hf;                       // exact
    asm("cvt.rn.f16.f32 %0, %1;" : "=h"(l) : "f"(r));
}
__device__ __forceinline__ uint32_t pack2(uint16_t a, uint16_t b) {
    return (uint32_t)a | ((uint32_t)b << 16);
}
__device__ __forceinline__ uint32_t smem_u32p(const void* p) {
    uint32_t a;
    asm("{ .reg .u64 t; cvta.to.shared.u64 t, %1; cvt.u32.u64 %0, t; }" : "=r"(a) : "l"(p));
    return a;
}

#define MMA_BF16(d, a, b) \
    asm volatile("mma.sync.aligned.m16n8k16.row.col.f32.bf16.bf16.f32 " \
        "{%0,%1,%2,%3}, {%4,%5,%6,%7}, {%8,%9}, {%0,%1,%2,%3};" \
        : "+f"((d)[0]), "+f"((d)[1]), "+f"((d)[2]), "+f"((d)[3]) \
        : "r"((a)[0]), "r"((a)[1]), "r"((a)[2]), "r"((a)[3]), \
          "r"((b)[0]), "r"((b)[1]))

#define MMA_F16(d, a, b) \
    asm volatile("mma.sync.aligned.m16n8k16.row.col.f32.f16.f16.f32 " \
        "{%0,%1,%2,%3}, {%4,%5,%6,%7}, {%8,%9}, {%0,%1,%2,%3};" \
        : "+f"((d)[0]), "+f"((d)[1]), "+f"((d)[2]), "+f"((d)[3]) \
        : "r"((a)[0]), "r"((a)[1]), "r"((a)[2]), "r"((a)[3]), \
          "r"((b)[0]), "r"((b)[1]))

#define LDSM4(r0, r1, r2, r3, a) \
    asm volatile("ldmatrix.sync.aligned.m8n8.x4.shared.b16 {%0,%1,%2,%3}, [%4];" \
        : "=r"(r0), "=r"(r1), "=r"(r2), "=r"(r3) : "r"(a))

__device__ __forceinline__ void cpa16(uint32_t sa, const void* ga) {
    asm volatile("cp.async.cg.shared.global [%0], [%1], 16;" :: "r"(sa), "l"(ga));
}
#define CP_COMMIT() asm volatile("cp.async.commit_group;" ::: "memory")
#define CP_WAIT0()  asm volatile("cp.async.wait_group 0;" ::: "memory")

// ---------------- fp32 -> packed f16x2 hi/lo split ----------------
__global__ void split_pack_f16(const float* __restrict__ in,
                               uint32_t* __restrict__ oh, uint32_t* __restrict__ ol, int n8)
{
    int i = blockIdx.x * blockDim.x + threadIdx.x;
    if (i >= n8) return;
    float4 a = ((const float4*)in)[2 * i];
    float4 b = ((const float4*)in)[2 * i + 1];
    uint16_t h[8], l[8];
    split_f16(a.x, h[0], l[0]); split_f16(a.y, h[1], l[1]);
    split_f16(a.z, h[2], l[2]); split_f16(a.w, h[3], l[3]);
    split_f16(b.x, h[4], l[4]); split_f16(b.y, h[5], l[5]);
    split_f16(b.z, h[6], l[6]); split_f16(b.w, h[7], l[7]);
    ((uint4*)oh)[i] = make_uint4(pack2(h[0],h[1]), pack2(h[2],h[3]), pack2(h[4],h[5]), pack2(h[6],h[7]));
    ((uint4*)ol)[i] = make_uint4(pack2(l[0],l[1]), pack2(l[2],l[3]), pack2(l[4],l[5]), pack2(l[6],l[7]));
}

// ===== 2-term fp16 GEMM: C = (Ah+Al)·Bh^T, multi-segment N (fused QKV) =====
#define STRP 20
#define PART_U32 (128 * STRP)               // 2560
#define BUF_U32  (3 * PART_U32)             // Ah, Al, Bh
#define GEMM_SMEM (2 * BUF_U32 * 4)         // 61440 B

__global__ __launch_bounds__(256, 2) void gemm_f16_2t(
    int M, int K, int tiles0, int tiles01,
    const uint32_t* __restrict__ Ah, const uint32_t* __restrict__ Al,
    const uint32_t* __restrict__ Bh0, float* __restrict__ C0, int N0,
    const uint32_t* __restrict__ Bh1, float* __restrict__ C1, int N1,
    const uint32_t* __restrict__ Bh2, float* __restrict__ C2, int N2)
{
    extern __shared__ uint32_t s32[];
    const uint32_t sb = smem_u32p(s32);

    const int nt = blockIdx.x;
    const uint32_t* Bh; float* C; int N, ntl;
    if (nt < tiles0)       { Bh = Bh0; C = C0; N = N0; ntl = nt; }
    else if (nt < tiles01) { Bh = Bh1; C = C1; N = N1; ntl = nt - tiles0; }
    else                   { Bh = Bh2; C = C2; N = N2; ntl = nt - tiles01; }

    const int tid    = threadIdx.x;
    const int wid    = tid >> 5;
    const int lane   = tid & 31;
    const int quad   = lane >> 2;
    const int tq     = lane & 3;
    const int warp_m = wid & 3;
    const int warp_n = wid >> 2;
    const int m0 = blockIdx.y << 7;
    const int n0 = ntl << 7;
    const int K2 = K >> 1;

    const int jm   = lane >> 3, jr = lane & 7;
    const int a_ro = (jm & 1) * 8 + jr;
    const int a_ko = (jm >> 1) * 4;
    const int b_go = jm >> 1;
    const int b_ko = (jm & 1) * 4;

    const uint32_t* pAh = Ah + (size_t)m0 * K2;
    const uint32_t* pAl = Al + (size_t)m0 * K2;
    const uint32_t* pBh = Bh + (size_t)n0 * K2;

    const int r0_ = tid >> 2;
    const int r1_ = 64 + r0_;
    const int qd  = (tid & 3) * 4;

#define LOADP(it, buf) do { \
    int kp = (it) * 16; \
    uint32_t sbase = sb + (uint32_t)(buf) * BUF_U32 * 4u; \
    cpa16(sbase + (uint32_t)(0*PART_U32 + r0_*STRP + qd)*4u, pAh + (size_t)r0_*K2 + kp + qd); \
    cpa16(sbase + (uint32_t)(0*PART_U32 + r1_*STRP + qd)*4u, pAh + (size_t)r1_*K2 + kp + qd); \
    cpa16(sbase + (uint32_t)(1*PART_U32 + r0_*STRP + qd)*4u, pAl + (size_t)r0_*K2 + kp + qd); \
    cpa16(sbase + (uint32_t)(1*PART_U32 + r1_*STRP + qd)*4u, pAl + (size_t)r1_*K2 + kp + qd); \
    cpa16(sbase + (uint32_t)(2*PART_U32 + r0_*STRP + qd)*4u, pBh + (size_t)r0_*K2 + kp + qd); \
    cpa16(sbase + (uint32_t)(2*PART_U32 + r1_*STRP + qd)*4u, pBh + (size_t)r1_*K2 + kp + qd); \
    CP_COMMIT(); \
} while (0)

    float acc[2][8][4];
#pragma unroll
    for (int mf = 0; mf < 2; mf++)
#pragma unroll
        for (int nf = 0; nf < 8; nf++)
#pragma unroll
            for (int r = 0; r < 4; r++) acc[mf][nf][r] = 0.f;

    const int NT = K / 32;

    LOADP(0, 0);

    for (int it = 0; it < NT; ++it) {
        CP_WAIT0();
        __syncthreads();
        if (it + 1 < NT) LOADP(it + 1, (it + 1) & 1);

        const uint32_t sA = sb + (uint32_t)(it & 1) * BUF_U32 * 4u;
        const uint32_t sB = sA + 2u * PART_U32 * 4u;

#pragma unroll
        for (int ks = 0; ks < 2; ks++) {
            const int kb = ks * 8;
            uint32_t ah[2][4], al[2][4];
#pragma unroll
            for (int mf = 0; mf < 2; mf++) {
                uint32_t ar = sA + (uint32_t)((warp_m*32 + mf*16 + a_ro) * STRP + kb + a_ko) * 4u;
                LDSM4(ah[mf][0], ah[mf][1], ah[mf][2], ah[mf][3], ar);
                LDSM4(al[mf][0], al[mf][1], al[mf][2], al[mf][3], ar + PART_U32*4u);
            }
#pragma unroll
            for (int g = 0; g < 4; g++) {
                uint32_t br = sB + (uint32_t)((warp_n*64 + (2*g + b_go)*8 + jr) * STRP + kb + b_ko) * 4u;
                uint32_t b0h[2], b1h[2];
                LDSM4(b0h[0], b0h[1], b1h[0], b1h[1], br);
#pragma unroll
                for (int mf = 0; mf < 2; mf++) {
                    MMA_F16(acc[mf][2*g],   ah[mf], b0h);
                    MMA_F16(acc[mf][2*g],   al[mf], b0h);
                    MMA_F16(acc[mf][2*g+1], ah[mf], b1h);
                    MMA_F16(acc[mf][2*g+1], al[mf], b1h);
                }
            }
        }
    }

#pragma unroll
    for (int mf = 0; mf < 2; mf++) {
        int row = m0 + warp_m * 32 + mf * 16 + quad;
#pragma unroll
        for (int nf = 0; nf < 8; nf++) {
            int col = n0 + warp_n * 64 + nf * 8 + tq * 2;
            *(float2*)(C + (size_t)row * N + col)       = make_float2(acc[mf][nf][0], acc[mf][nf][1]);
            *(float2*)(C + (size_t)(row + 8) * N + col) = make_float2(acc[mf][nf][2], acc[mf][nf][3]);
        }
    }
#undef LOADP
}

// ---------------- fused RMSNorm + RoPE -> packed bf16x2 hi/lo ----------------
__global__ void rmsnorm_rope_pack(const float* __restrict__ in, const float* __restrict__ gamma,
                                  uint32_t* __restrict__ oh, uint32_t* __restrict__ ol,
                                  int nrows, int heads)
{
    int gw   = (int)((blockIdx.x * blockDim.x + threadIdx.x) >> 5);
    int lane = threadIdx.x & 31;
    if (gw >= nrows) return;
    int bt = gw / heads;
    int t  = bt & (T_SEQ - 1);

    const float* row = in + (size_t)gw * HD;

    float v[8];
    *(float4*)&v[0] = *(const float4*)(row + lane * 8);
    *(float4*)&v[4] = *(const float4*)(row + lane * 8 + 4);

    float ss = 0.f;
#pragma unroll
    for (int i = 0; i < 8; i++) ss += v[i] * v[i];
#pragma unroll
    for (int o = 16; o > 0; o >>= 1) ss += __shfl_xor_sync(0xffffffffu, ss, o);

    float r = rsqrtf(ss * (1.0f / HD) + 1e-6f);

    float g[8];
    *(float4*)&g[0] = *(const float4*)(gamma + lane * 8);
    *(float4*)&g[4] = *(const float4*)(gamma + lane * 8 + 4);

    float invf[4];
    *(float4*)invf = *(const float4*)(g_invf + lane * 4);

    float tf = (float)t;
#pragma unroll
    for (int p = 0; p < 4; p++) {
        float ang = tf * invf[p];
        float c, s;
        sincosf(ang, &s, &c);
        float x0 = v[2 * p]     * r * g[2 * p];
        float x1 = v[2 * p + 1] * r * g[2 * p + 1];
        v[2 * p]     = x0 * c - x1 * s;
        v[2 * p + 1] = x0 * s + x1 * c;
    }

    uint16_t hh[8], ll[8];
#pragma unroll
    for (int i = 0; i < 8; i++) split_bf16(v[i], hh[i], ll[i]);
    size_t ob = (size_t)gw * (HD / 2) + lane * 4;
    *(uint4*)(oh + ob) = make_uint4(pack2(hh[0],hh[1]), pack2(hh[2],hh[3]),
                                    pack2(hh[4],hh[5]), pack2(hh[6],hh[7]));
    *(uint4*)(ol + ob) = make_uint4(pack2(ll[0],ll[1]), pack2(ll[2],ll[3]),
                                    pack2(ll[4],ll[5]), pack2(ll[6],ll[7]));
}

// ---------------- V transpose + split (bf16) ----------------
#define VT_SMEM (256 * 69 * 4)
__global__ __launch_bounds__(256) void transpose_split_v(
    const float* __restrict__ v, uint32_t* __restrict__ vth, uint32_t* __restrict__ vtl)
{
    extern __shared__ float st[];
    int b = blockIdx.y, t0 = blockIdx.x * 64;
    int tid = threadIdx.x;
    const float* vb = v + ((size_t)(b * T_SEQ + t0)) * HD;
#pragma unroll
    for (int i = 0; i < 16; i++) {
        int f = i * 256 + tid;
        int t = f >> 6, d4 = (f & 63) * 4;
        float4 x = *(const float4*)(vb + (size_t)t * HD + d4);
        st[(d4 + 0) * 69 + t] = x.x;
        st[(d4 + 1) * 69 + t] = x.y;
        st[(d4 + 2) * 69 + t] = x.z;
        st[(d4 + 3) * 69 + t] = x.w;
    }
    __syncthreads();
    int w = tid >> 5, l = tid & 31;
#pragma unroll
    for (int pass = 0; pass < 32; pass++) {
        int d = pass * 8 + w;
        float x0 = st[d * 69 + 2 * l];
        float x1 = st[d * 69 + 2 * l + 1];
        uint16_t h0, l0, h1, l1;
        split_bf16(x0, h0, l0); split_bf16(x1, h1, l1);
        size_t o = ((size_t)(b * HD + d)) * (T_SEQ / 2) + (t0 >> 1) + l;
        vth[o] = pack2(h0, h1);
        vtl[o] = pack2(l0, l1);
    }
}

// =========== sliding-window flash attention (bf16 3-term; ao -> packed fp16) ===========
#define AQ_STR 132
#define AV_STR 36
#define OFF_QH   0
#define OFF_QL   (64 * AQ_STR)
#define OFF_KVH  (2 * 64 * AQ_STR)
#define OFF_KVL  (OFF_KVH + 9216)
#define OFF_PH   (OFF_KVL + 9216)
#define OFF_PL   (OFF_PH + 64 * AV_STR)
#define OFF_RED  (OFF_PL + 64 * AV_STR)
#define OFF_RED2 (OFF_RED + 256)
#define OFF_MS   (OFF_RED2 + 256)
#define OFF_LS   (OFF_MS + 64)
#define ATTN_U32 (OFF_LS + 64)
#define ATTN_SMEM (ATTN_U32 * 4)

__global__ __launch_bounds__(256, 1) void attn_swa_mma(
    const uint32_t* __restrict__ Qph, const uint32_t* __restrict__ Qpl,
    const uint32_t* __restrict__ Kph, const uint32_t* __restrict__ Kpl,
    const uint32_t* __restrict__ Vth, const uint32_t* __restrict__ Vtl,
    uint32_t* __restrict__ Oh, uint32_t* __restrict__ Ol)
{
    extern __shared__ uint32_t s[];
    const uint32_t sb = smem_u32p(s);
    uint32_t* Ph   = s + OFF_PH;
    uint32_t* Pl   = s + OFF_PL;
    float* red     = (float*)(s + OFF_RED);
    float* red2    = (float*)(s + OFF_RED2);
    float* m_s     = (float*)(s + OFF_MS);
    float* l_s     = (float*)(s + OFF_LS);

    const int tid  = threadIdx.x;
    const int wid  = tid >> 5, lane = tid & 31, quad = lane >> 2, tq = lane & 3;
    const int wm   = wid & 1, wn = wid >> 1;
    const int jm   = lane >> 3, jr = lane & 7;
    const int a_ro = (jm & 1) * 8 + jr;
    const int a_ko = (jm >> 1) * 4;
    const int b_go = jm >> 1;
    const int b_ko = (jm & 1) * 4;
    const int qt   = blockIdx.x & 63;
    const int h    = (blockIdx.x >> 6) & 3;
    const int b    = blockIdx.x >> 8;
    const int q0   = qt << 6;

    const uint32_t* qh_g = Qph + ((size_t)(b * T_SEQ + q0)) * (CDIM / 2) + h * (HD / 2);
    const uint32_t* ql_g = Qpl + ((size_t)(b * T_SEQ + q0)) * (CDIM / 2) + h * (HD / 2);
    const uint32_t* kh_g = Kph + (size_t)b * T_SEQ * (HD / 2);
    const uint32_t* kl_g = Kpl + (size_t)b * T_SEQ * (HD / 2);
    const uint32_t* vh_g = Vth + (size_t)b * HD * (T_SEQ / 2);
    const uint32_t* vl_g = Vtl + (size_t)b * HD * (T_SEQ / 2);

#pragma unroll
    for (int i = 0; i < 8; i++) {
        int f = i * 256 + tid, row = f >> 5, c4 = (f & 31) * 4;
        cpa16(sb + (uint32_t)(OFF_QH + row * AQ_STR + c4) * 4u, qh_g + (size_t)row * (CDIM / 2) + c4);
        cpa16(sb + (uint32_t)(OFF_QL + row * AQ_STR + c4) * 4u, ql_g + (size_t)row * (CDIM / 2) + c4);
    }
    CP_COMMIT();
    if (tid < 64) { m_s[tid] = -1e30f; l_s[tid] = 0.f; }
    CP_WAIT0();
    __syncthreads();

    float oacc[2][8][4];
#pragma unroll
    for (int mf = 0; mf < 2; mf++)
#pragma unroll
        for (int nf = 0; nf < 8; nf++)
#pragma unroll
            for (int r = 0; r < 4; r++) oacc[mf][nf][r] = 0.f;

    int kt0 = q0 - WIN; if (kt0 < 0) kt0 = 0;

    for (int kt = kt0; kt <= q0; kt += 64) {
        __syncthreads();   // A

#pragma unroll
        for (int i = 0; i < 8; i++) {
            int f = i * 256 + tid, row = f >> 5, c4 = (f & 31) * 4;
            cpa16(sb + (uint32_t)(OFF_KVH + row * AQ_STR + c4) * 4u, kh_g + (size_t)(kt + row) * (HD / 2) + c4);
            cpa16(sb + (uint32_t)(OFF_KVL + row * AQ_STR + c4) * 4u, kl_g + (size_t)(kt + row) * (HD / 2) + c4);
        }
        CP_COMMIT();
        CP_WAIT0();
        __syncthreads();   // B

        float sacc[2][2][4];
#pragma unroll
        for (int mf = 0; mf < 2; mf++)
#pragma unroll
            for (int nf = 0; nf < 2; nf++)
#pragma unroll
                for (int r = 0; r < 4; r++) sacc[mf][nf][r] = 0.f;

#pragma unroll
        for (int ks = 0; ks < 16; ks++) {
            const int kb = ks * 8;
            uint32_t ah[2][4], al[2][4];
#pragma unroll
            for (int mf = 0; mf < 2; mf++) {
                uint32_t ar = sb + (uint32_t)(OFF_QH + (wm*32 + mf*16 + a_ro) * AQ_STR + kb + a_ko) * 4u;
                LDSM4(ah[mf][0], ah[mf][1], ah[mf][2], ah[mf][3], ar);
                LDSM4(al[mf][0], al[mf][1], al[mf][2], al[mf][3], ar + (OFF_QL - OFF_QH) * 4u);
            }
            uint32_t br = sb + (uint32_t)(OFF_KVH + (wn*16 + b_go*8 + jr) * AQ_STR + kb + b_ko) * 4u;
            uint32_t b0h[2], b1h[2], b0l[2], b1l[2];
            LDSM4(b0h[0], b0h[1], b1h[0], b1h[1], br);
            LDSM4(b0l[0], b0l[1], b1l[0], b1l[1], br + (OFF_KVL - OFF_KVH) * 4u);
#pragma unroll
            for (int mf = 0; mf < 2; mf++) {
                MMA_BF16(sacc[mf][0], ah[mf], b0h);
                MMA_BF16(sacc[mf][0], ah[mf], b0l);
                MMA_BF16(sacc[mf][0], al[mf], b0h);
                MMA_BF16(sacc[mf][1], ah[mf], b1h);
                MMA_BF16(sacc[mf][1], ah[mf], b1l);
                MMA_BF16(sacc[mf][1], al[mf], b1h);
            }
        }

#pragma unroll
        for (int mf = 0; mf < 2; mf++)
#pragma unroll
            for (int half = 0; half < 2; half++) {
                int rowl = wm * 32 + mf * 16 + quad + half * 8;
                int irow = q0 + rowl;
                float mt = -1e30f;
#pragma unroll
                for (int nf = 0; nf < 2; nf++)
#pragma unroll
                    for (int p = 0; p < 2; p++) {
                        int j = kt + wn * 16 + nf * 8 + tq * 2 + p;
                        bool ok = (j <= irow) && (j >= irow - WIN);
                        float x = ok ? sacc[mf][nf][half * 2 + p] * 0.0625f : -1e30f;
                        sacc[mf][nf][half * 2 + p] = x;
                        mt = fmaxf(mt, x);
                    }
                mt = fmaxf(mt, __shfl_xor_sync(0xffffffffu, mt, 1));
                mt = fmaxf(mt, __shfl_xor_sync(0xffffffffu, mt, 2));
                if (tq == 0) red[wn * 64 + rowl] = mt;
            }
        __syncthreads();   // C

#pragma unroll
        for (int i = 0; i < 8; i++) {
            int f = i * 256 + tid, d = f >> 3, c4 = (f & 7) * 4;
            cpa16(sb + (uint32_t)(OFF_KVH + d * AV_STR + c4) * 4u, vh_g + (size_t)d * (T_SEQ / 2) + (kt >> 1) + c4);
            cpa16(sb + (uint32_t)(OFF_KVL + d * AV_STR + c4) * 4u, vl_g + (size_t)d * (T_SEQ / 2) + (kt >> 1) + c4);
        }
        CP_COMMIT();

        float mn_loc[2][2], corr_loc[2][2];
#pragma unroll
        for (int mf = 0; mf < 2; mf++)
#pragma unroll
            for (int half = 0; half < 2; half++) {
                int rowl = wm * 32 + mf * 16 + quad + half * 8;
                float mt = fmaxf(fmaxf(red[rowl], red[64 + rowl]),
                                 fmaxf(red[128 + rowl], red[192 + rowl]));
                float mo = m_s[rowl];
                float mn = fmaxf(mo, mt);
                mn_loc[mf][half]   = mn;
                corr_loc[mf][half] = __expf(mo - mn);
            }

#pragma unroll
        for (int mf = 0; mf < 2; mf++)
#pragma unroll
            for (int half = 0; half < 2; half++) {
                int rowl = wm * 32 + mf * 16 + quad + half * 8;
                float mn = mn_loc[mf][half];
                float rs = 0.f;
#pragma unroll
                for (int nf = 0; nf < 2; nf++) {
                    float p0 = __expf(sacc[mf][nf][half * 2 + 0] - mn);
                    float p1 = __expf(sacc[mf][nf][half * 2 + 1] - mn);
                    rs += p0 + p1;
                    uint16_t h0, l0, h1, l1;
                    split_bf16(p0, h0, l0); split_bf16(p1, h1, l1);
                    int o = rowl * AV_STR + wn * 8 + nf * 4 + tq;
                    Ph[o] = pack2(h0, h1);
                    Pl[o] = pack2(l0, l1);
                }
                rs += __shfl_xor_sync(0xffffffffu, rs, 1);
                rs += __shfl_xor_sync(0xffffffffu, rs, 2);
                if (tq == 0) red2[wn * 64 + rowl] = rs;
            }
        __syncthreads();   // E

        if (wid < 2 && tq == 0) {
#pragma unroll
            for (int mf = 0; mf < 2; mf++)
#pragma unroll
                for (int half = 0; half < 2; half++) {
                    int rowl = wid * 32 + mf * 16 + quad + half * 8;
                    l_s[rowl] = l_s[rowl] * corr_loc[mf][half] +
                                red2[rowl] + red2[64 + rowl] + red2[128 + rowl] + red2[192 + rowl];
                    m_s[rowl] = mn_loc[mf][half];
                }
        }
#pragma unroll
        for (int mf = 0; mf < 2; mf++) {
            float c0 = corr_loc[mf][0], c1 = corr_loc[mf][1];
#pragma unroll
            for (int nf = 0; nf < 8; nf++) {
                oacc[mf][nf][0] *= c0; oacc[mf][nf][1] *= c0;
                oacc[mf][nf][2] *= c1; oacc[mf][nf][3] *= c1;
            }
        }
        CP_WAIT0();
        __syncthreads();   // F

#pragma unroll
        for (int kk = 0; kk < 4; kk++) {
            const int kb = kk * 8;
            uint32_t pah[2][4], pal[2][4];
#pragma unroll
            for (int mf = 0; mf < 2; mf++) {
                uint32_t ar = sb + (uint32_t)(OFF_PH + (wm*32 + mf*16 + a_ro) * AV_STR + kb + a_ko) * 4u;
                LDSM4(pah[mf][0], pah[mf][1], pah[mf][2], pah[mf][3], ar);
                LDSM4(pal[mf][0], pal[mf][1], pal[mf][2], pal[mf][3], ar + (OFF_PL - OFF_PH) * 4u);
            }
#pragma unroll
            for (int g = 0; g < 4; g++) {
                uint32_t br = sb + (uint32_t)(OFF_KVH + (wn*64 + (2*g + b_go)*8 + jr) * AV_STR + kb + b_ko) * 4u;
                uint32_t v0h[2], v1h[2], v0l[2], v1l[2];
                LDSM4(v0h[0], v0h[1], v1h[0], v1h[1], br);
                LDSM4(v0l[0], v0l[1], v1l[0], v1l[1], br + (OFF_KVL - OFF_KVH) * 4u);
#pragma unroll
                for (int mf = 0; mf < 2; mf++) {
                    MMA_BF16(oacc[mf][2*g],   pah[mf], v0h);
                    MMA_BF16(oacc[mf][2*g],   pah[mf], v0l);
                    MMA_BF16(oacc[mf][2*g],   pal[mf], v0h);
                    MMA_BF16(oacc[mf][2*g+1], pah[mf], v1h);
                    MMA_BF16(oacc[mf][2*g+1], pah[mf], v1l);
                    MMA_BF16(oacc[mf][2*g+1], pal[mf], v1h);
                }
            }
        }
    }

    // ---- epilogue: write ao directly as packed f16x2 hi/lo (Wo GEMM operand) ----
#pragma unroll
    for (int mf = 0; mf < 2; mf++) {
        int r0 = wm * 32 + mf * 16 + quad;
        float i0 = 1.f / l_s[r0], i1 = 1.f / l_s[r0 + 8];
        size_t base0 = ((size_t)(b * T_SEQ + q0 + r0)) * (CDIM / 2) + h * (HD / 2);
        size_t base1 = base0 + 8 * (CDIM / 2);
#pragma unroll
        for (int nf = 0; nf < 8; nf++) {
            int cp_ = wn * 32 + nf * 4 + tq;
            uint16_t h0, l0, h1, l1;
            split_f16(oacc[mf][nf][0] * i0, h0, l0);
            split_f16(oacc[mf][nf][1] * i0, h1, l1);
            Oh[base0 + cp_] = pack2(h0, h1);
            Ol[base0 + cp_] = pack2(l0, l1);
            split_f16(oacc[mf][nf][2] * i1, h0, l0);
            split_f16(oacc[mf][nf][3] * i1, h1, l1);
            Oh[base1 + cp_] = pack2(h0, h1);
            Ol[base1 + cp_] = pack2(l0, l1);
        }
    }
}

// ---------------- launch ----------------
extern "C" void kernel_launch(void* const* d_in, const int* in_sizes, int n_in,
                              void* d_out, int out_size)
{
    const float* x  = (const float*)d_in[0];
    const float* Wq = (const float*)d_in[1];
    const float* Wk = (const float*)d_in[2];
    const float* Wv = (const float*)d_in[3];
    const float* Wo = (const float*)d_in[4];
    const float* qg = (const float*)d_in[5];
    const float* kg = (const float*)d_in[6];
    float* out = (float*)d_out;

    float *q, *k, *v;
    uint32_t *xh, *xl, *aoh, *aol, *wqh, *wql, *wkh, *wkl, *wvh, *wvl, *woh, *wol;
    uint32_t *qph, *qpl, *kph, *kpl, *vth, *vtl;
    cudaGetSymbolAddress((void**)&q,   g_q);
    cudaGetSymbolAddress((void**)&k,   g_k);
    cudaGetSymbolAddress((void**)&v,   g_v);
    cudaGetSymbolAddress((void**)&xh,  g_xh);
    cudaGetSymbolAddress((void**)&xl,  g_xl);
    cudaGetSymbolAddress((void**)&aoh, g_aoh);
    cudaGetSymbolAddress((void**)&aol, g_aol);
    cudaGetSymbolAddress((void**)&wqh, g_wqh);
    cudaGetSymbolAddress((void**)&wql, g_wql);
    cudaGetSymbolAddress((void**)&wkh, g_wkh);
    cudaGetSymbolAddress((void**)&wkl, g_wkl);
    cudaGetSymbolAddress((void**)&wvh, g_wvh);
    cudaGetSymbolAddress((void**)&wvl, g_wvl);
    cudaGetSymbolAddress((void**)&woh, g_woh);
    cudaGetSymbolAddress((void**)&wol, g_wol);
    cudaGetSymbolAddress((void**)&qph, g_qph);
    cudaGetSymbolAddress((void**)&qpl, g_qpl);
    cudaGetSymbolAddress((void**)&kph, g_kph);
    cudaGetSymbolAddress((void**)&kpl, g_kpl);
    cudaGetSymbolAddress((void**)&vth, g_vth);
    cudaGetSymbolAddress((void**)&vtl, g_vtl);

    const int M = BATCH * T_SEQ;   // 8192

    init_invf<<<1, 128>>>();

    // pre-split: x needs hi+lo; weights need hi only (lo written but unused)
    split_pack_f16<<<(M * CDIM / 8 + 255) / 256, 256>>>(x,  xh,  xl,  M * CDIM / 8);
    split_pack_f16<<<(CDIM * CDIM / 8 + 255) / 256, 256>>>(Wq, wqh, wql, CDIM * CDIM / 8);
    split_pack_f16<<<(HD * CDIM / 8 + 255) / 256, 256>>>(Wk, wkh, wkl, HD * CDIM / 8);
    split_pack_f16<<<(HD * CDIM / 8 + 255) / 256, 256>>>(Wv, wvh, wvl, HD * CDIM / 8);
    split_pack_f16<<<(CDIM * CDIM / 8 + 255) / 256, 256>>>(Wo, woh, wol, CDIM * CDIM / 8);

    cudaFuncSetAttribute(gemm_f16_2t, cudaFuncAttributeMaxDynamicSharedMemorySize, GEMM_SMEM);

    // fused Q+K+V projection: n-tiles 0-7 -> Wq/q, 8-9 -> Wk/k, 10-11 -> Wv/v
    gemm_f16_2t<<<dim3(12, M / 128), 256, GEMM_SMEM>>>(
        M, CDIM, 8, 10, xh, xl,
        wqh, q, CDIM,
        wkh, k, HD,
        wvh, v, HD);

    rmsnorm_rope_pack<<<(M * NH) / 8, 256>>>(q, qg, qph, qpl, M * NH, NH);
    rmsnorm_rope_pack<<<M / 8, 256>>>(k, kg, kph, kpl, M, 1);

    cudaFuncSetAttribute(transpose_split_v, cudaFuncAttributeMaxDynamicSharedMemorySize, VT_SMEM);
    transpose_split_v<<<dim3(T_SEQ / 64, BATCH), 256, VT_SMEM>>>(v, vth, vtl);

    cudaFuncSetAttribute(attn_swa_mma, cudaFuncAttributeMaxDynamicSharedMemorySize, ATTN_SMEM);
    attn_swa_mma<<<BATCH * NH * (T_SEQ / 64), 256, ATTN_SMEM>>>(
        qph, qpl, kph, kpl, vth, vtl, aoh, aol);

    // output projection (consumes packed fp16 ao from attention epilogue)
    gemm_f16_2t<<<dim3(8, M / 128), 256, GEMM_SMEM>>>(
        M, CDIM, 8, 8, aoh, aol,
        woh, out, CDIM,
        woh, out, CDIM,
        woh, out, CDIM);
}

// round 13
// speedup vs baseline: 2.8353x; 1.1068x over previous
#include <cuda_runtime.h>
#include <math.h>
#include <stdint.h>

#define T_SEQ 4096
#define BATCH 2
#define CDIM  1024
#define HD    256
#define NH    4
#define WIN   512

// ---------------- scratch (static device globals; no allocation) ----------------
__device__ float    g_q [(size_t)BATCH * T_SEQ * CDIM];
__device__ float    g_k [(size_t)BATCH * T_SEQ * HD];
__device__ float    g_v [(size_t)BATCH * T_SEQ * HD];
__device__ float    g_invf[HD / 2];
// packed f16x2 hi/lo operand buffers (GEMM)
__device__ uint32_t g_xh [(size_t)BATCH * T_SEQ * CDIM / 2];
__device__ uint32_t g_xl [(size_t)BATCH * T_SEQ * CDIM / 2];
__device__ uint32_t g_aoh[(size_t)BATCH * T_SEQ * CDIM / 2];
__device__ uint32_t g_aol[(size_t)BATCH * T_SEQ * CDIM / 2];
__device__ uint32_t g_wqh[CDIM * CDIM / 2];
__device__ uint32_t g_wql[CDIM * CDIM / 2];
__device__ uint32_t g_wkh[HD * CDIM / 2];
__device__ uint32_t g_wkl[HD * CDIM / 2];
__device__ uint32_t g_wvh[HD * CDIM / 2];
__device__ uint32_t g_wvl[HD * CDIM / 2];
__device__ uint32_t g_woh[CDIM * CDIM / 2];
__device__ uint32_t g_wol[CDIM * CDIM / 2];
// pre-split fp16 attention operands (Q hi/lo; K hi; V^T hi)
__device__ uint32_t g_qph[(size_t)BATCH * T_SEQ * CDIM / 2];
__device__ uint32_t g_qpl[(size_t)BATCH * T_SEQ * CDIM / 2];
__device__ uint32_t g_kph[(size_t)BATCH * T_SEQ * HD / 2];
__device__ uint32_t g_kpl[(size_t)BATCH * T_SEQ * HD / 2];
__device__ uint32_t g_vth[(size_t)BATCH * HD * T_SEQ / 2];

// ---------------- RoPE inv_freq table ----------------
__global__ void init_invf()
{
    int i = threadIdx.x;
    float e = (float)(2 * i) * (1.0f / HD);
    g_invf[i] = (float)pow(1000000.0, -(double)e);
}

// ---------------- common helpers ----------------
__device__ __forceinline__ void split_f16(float x, uint16_t& h, uint16_t& l) {
    asm("cvt.rn.f16.f32 %0, %1;" : "=h"(h) : "f"(x));
    float hf;
    asm("cvt.f32.f16 %0, %1;" : "=f"(hf) : "h"(h));
    float r = x - hf;                       // exact
    asm("cvt.rn.f16.f32 %0, %1;" : "=h"(l) : "f"(r));
}
__device__ __forceinline__ uint16_t to_f16(float x) {
    uint16_t h;
    asm("cvt.rn.f16.f32 %0, %1;" : "=h"(h) : "f"(x));
    return h;
}
__device__ __forceinline__ uint32_t pack2(uint16_t a, uint16_t b) {
    return (uint32_t)a | ((uint32_t)b << 16);
}
__device__ __forceinline__ uint32_t smem_u32p(const void* p) {
    uint32_t a;
    asm("{ .reg .u64 t; cvta.to.shared.u64 t, %1; cvt.u32.u64 %0, t; }" : "=r"(a) : "l"(p));
    return a;
}

#define MMA_F16(d, a, b) \
    asm volatile("mma.sync.aligned.m16n8k16.row.col.f32.f16.f16.f32 " \
        "{%0,%1,%2,%3}, {%4,%5,%6,%7}, {%8,%9}, {%0,%1,%2,%3};" \
        : "+f"((d)[0]), "+f"((d)[1]), "+f"((d)[2]), "+f"((d)[3]) \
        : "r"((a)[0]), "r"((a)[1]), "r"((a)[2]), "r"((a)[3]), \
          "r"((b)[0]), "r"((b)[1]))

#define LDSM4(r0, r1, r2, r3, a) \
    asm volatile("ldmatrix.sync.aligned.m8n8.x4.shared.b16 {%0,%1,%2,%3}, [%4];" \
        : "=r"(r0), "=r"(r1), "=r"(r2), "=r"(r3) : "r"(a))

__device__ __forceinline__ void cpa16(uint32_t sa, const void* ga) {
    asm volatile("cp.async.cg.shared.global [%0], [%1], 16;" :: "r"(sa), "l"(ga));
}
#define CP_COMMIT() asm volatile("cp.async.commit_group;" ::: "memory")
#define CP_WAIT0()  asm volatile("cp.async.wait_group 0;" ::: "memory")

// ---------------- fp32 -> packed f16x2 hi/lo split ----------------
__global__ void split_pack_f16(const float* __restrict__ in,
                               uint32_t* __restrict__ oh, uint32_t* __restrict__ ol, int n8)
{
    int i = blockIdx.x * blockDim.x + threadIdx.x;
    if (i >= n8) return;
    float4 a = ((const float4*)in)[2 * i];
    float4 b = ((const float4*)in)[2 * i + 1];
    uint16_t h[8], l[8];
    split_f16(a.x, h[0], l[0]); split_f16(a.y, h[1], l[1]);
    split_f16(a.z, h[2], l[2]); split_f16(a.w, h[3], l[3]);
    split_f16(b.x, h[4], l[4]); split_f16(b.y, h[5], l[5]);
    split_f16(b.z, h[6], l[6]); split_f16(b.w, h[7], l[7]);
    ((uint4*)oh)[i] = make_uint4(pack2(h[0],h[1]), pack2(h[2],h[3]), pack2(h[4],h[5]), pack2(h[6],h[7]));
    ((uint4*)ol)[i] = make_uint4(pack2(l[0],l[1]), pack2(l[2],l[3]), pack2(l[4],l[5]), pack2(l[6],l[7]));
}

// ===== 2-term fp16 GEMM: C = (Ah+Al)·Bh^T, multi-segment N (fused QKV) =====
#define STRP 20
#define PART_U32 (128 * STRP)               // 2560
#define BUF_U32  (3 * PART_U32)             // Ah, Al, Bh
#define GEMM_SMEM (2 * BUF_U32 * 4)         // 61440 B

__global__ __launch_bounds__(256, 2) void gemm_f16_2t(
    int M, int K, int tiles0, int tiles01,
    const uint32_t* __restrict__ Ah, const uint32_t* __restrict__ Al,
    const uint32_t* __restrict__ Bh0, float* __restrict__ C0, int N0,
    const uint32_t* __restrict__ Bh1, float* __restrict__ C1, int N1,
    const uint32_t* __restrict__ Bh2, float* __restrict__ C2, int N2)
{
    extern __shared__ uint32_t s32[];
    const uint32_t sb = smem_u32p(s32);

    const int nt = blockIdx.x;
    const uint32_t* Bh; float* C; int N, ntl;
    if (nt < tiles0)       { Bh = Bh0; C = C0; N = N0; ntl = nt; }
    else if (nt < tiles01) { Bh = Bh1; C = C1; N = N1; ntl = nt - tiles0; }
    else                   { Bh = Bh2; C = C2; N = N2; ntl = nt - tiles01; }

    const int tid    = threadIdx.x;
    const int wid    = tid >> 5;
    const int lane   = tid & 31;
    const int quad   = lane >> 2;
    const int tq     = lane & 3;
    const int warp_m = wid & 3;
    const int warp_n = wid >> 2;
    const int m0 = blockIdx.y << 7;
    const int n0 = ntl << 7;
    const int K2 = K >> 1;

    const int jm   = lane >> 3, jr = lane & 7;
    const int a_ro = (jm & 1) * 8 + jr;
    const int a_ko = (jm >> 1) * 4;
    const int b_go = jm >> 1;
    const int b_ko = (jm & 1) * 4;

    const uint32_t* pAh = Ah + (size_t)m0 * K2;
    const uint32_t* pAl = Al + (size_t)m0 * K2;
    const uint32_t* pBh = Bh + (size_t)n0 * K2;

    const int r0_ = tid >> 2;
    const int r1_ = 64 + r0_;
    const int qd  = (tid & 3) * 4;

#define LOADP(it, buf) do { \
    int kp = (it) * 16; \
    uint32_t sbase = sb + (uint32_t)(buf) * BUF_U32 * 4u; \
    cpa16(sbase + (uint32_t)(0*PART_U32 + r0_*STRP + qd)*4u, pAh + (size_t)r0_*K2 + kp + qd); \
    cpa16(sbase + (uint32_t)(0*PART_U32 + r1_*STRP + qd)*4u, pAh + (size_t)r1_*K2 + kp + qd); \
    cpa16(sbase + (uint32_t)(1*PART_U32 + r0_*STRP + qd)*4u, pAl + (size_t)r0_*K2 + kp + qd); \
    cpa16(sbase + (uint32_t)(1*PART_U32 + r1_*STRP + qd)*4u, pAl + (size_t)r1_*K2 + kp + qd); \
    cpa16(sbase + (uint32_t)(2*PART_U32 + r0_*STRP + qd)*4u, pBh + (size_t)r0_*K2 + kp + qd); \
    cpa16(sbase + (uint32_t)(2*PART_U32 + r1_*STRP + qd)*4u, pBh + (size_t)r1_*K2 + kp + qd); \
    CP_COMMIT(); \
} while (0)

    float acc[2][8][4];
#pragma unroll
    for (int mf = 0; mf < 2; mf++)
#pragma unroll
        for (int nf = 0; nf < 8; nf++)
#pragma unroll
            for (int r = 0; r < 4; r++) acc[mf][nf][r] = 0.f;

    const int NT = K / 32;

    LOADP(0, 0);

    for (int it = 0; it < NT; ++it) {
        CP_WAIT0();
        __syncthreads();
        if (it + 1 < NT) LOADP(it + 1, (it + 1) & 1);

        const uint32_t sA = sb + (uint32_t)(it & 1) * BUF_U32 * 4u;
        const uint32_t sB = sA + 2u * PART_U32 * 4u;

#pragma unroll
        for (int ks = 0; ks < 2; ks++) {
            const int kb = ks * 8;
            uint32_t ah[2][4], al[2][4];
#pragma unroll
            for (int mf = 0; mf < 2; mf++) {
                uint32_t ar = sA + (uint32_t)((warp_m*32 + mf*16 + a_ro) * STRP + kb + a_ko) * 4u;
                LDSM4(ah[mf][0], ah[mf][1], ah[mf][2], ah[mf][3], ar);
                LDSM4(al[mf][0], al[mf][1], al[mf][2], al[mf][3], ar + PART_U32*4u);
            }
#pragma unroll
            for (int g = 0; g < 4; g++) {
                uint32_t br = sB + (uint32_t)((warp_n*64 + (2*g + b_go)*8 + jr) * STRP + kb + b_ko) * 4u;
                uint32_t b0h[2], b1h[2];
                LDSM4(b0h[0], b0h[1], b1h[0], b1h[1], br);
#pragma unroll
                for (int mf = 0; mf < 2; mf++) {
                    MMA_F16(acc[mf][2*g],   ah[mf], b0h);
                    MMA_F16(acc[mf][2*g],   al[mf], b0h);
                    MMA_F16(acc[mf][2*g+1], ah[mf], b1h);
                    MMA_F16(acc[mf][2*g+1], al[mf], b1h);
                }
            }
        }
    }

#pragma unroll
    for (int mf = 0; mf < 2; mf++) {
        int row = m0 + warp_m * 32 + mf * 16 + quad;
#pragma unroll
        for (int nf = 0; nf < 8; nf++) {
            int col = n0 + warp_n * 64 + nf * 8 + tq * 2;
            *(float2*)(C + (size_t)row * N + col)       = make_float2(acc[mf][nf][0], acc[mf][nf][1]);
            *(float2*)(C + (size_t)(row + 8) * N + col) = make_float2(acc[mf][nf][2], acc[mf][nf][3]);
        }
    }
#undef LOADP
}

// ---------------- fused RMSNorm + RoPE -> packed f16x2 hi/lo ----------------
__global__ void rmsnorm_rope_pack(const float* __restrict__ in, const float* __restrict__ gamma,
                                  uint32_t* __restrict__ oh, uint32_t* __restrict__ ol,
                                  int nrows, int heads)
{
    int gw   = (int)((blockIdx.x * blockDim.x + threadIdx.x) >> 5);
    int lane = threadIdx.x & 31;
    if (gw >= nrows) return;
    int bt = gw / heads;
    int t  = bt & (T_SEQ - 1);

    const float* row = in + (size_t)gw * HD;

    float v[8];
    *(float4*)&v[0] = *(const float4*)(row + lane * 8);
    *(float4*)&v[4] = *(const float4*)(row + lane * 8 + 4);

    float ss = 0.f;
#pragma unroll
    for (int i = 0; i < 8; i++) ss += v[i] * v[i];
#pragma unroll
    for (int o = 16; o > 0; o >>= 1) ss += __shfl_xor_sync(0xffffffffu, ss, o);

    float r = rsqrtf(ss * (1.0f / HD) + 1e-6f);

    float g[8];
    *(float4*)&g[0] = *(const float4*)(gamma + lane * 8);
    *(float4*)&g[4] = *(const float4*)(gamma + lane * 8 + 4);

    float invf[4];
    *(float4*)invf = *(const float4*)(g_invf + lane * 4);

    float tf = (float)t;
#pragma unroll
    for (int p = 0; p < 4; p++) {
        float ang = tf * invf[p];
        float c, s;
        sincosf(ang, &s, &c);
        float x0 = v[2 * p]     * r * g[2 * p];
        float x1 = v[2 * p + 1] * r * g[2 * p + 1];
        v[2 * p]     = x0 * c - x1 * s;
        v[2 * p + 1] = x0 * s + x1 * c;
    }

    uint16_t hh[8], ll[8];
#pragma unroll
    for (int i = 0; i < 8; i++) split_f16(v[i], hh[i], ll[i]);
    size_t ob = (size_t)gw * (HD / 2) + lane * 4;
    *(uint4*)(oh + ob) = make_uint4(pack2(hh[0],hh[1]), pack2(hh[2],hh[3]),
                                    pack2(hh[4],hh[5]), pack2(hh[6],hh[7]));
    *(uint4*)(ol + ob) = make_uint4(pack2(ll[0],ll[1]), pack2(ll[2],ll[3]),
                                    pack2(ll[4],ll[5]), pack2(ll[6],ll[7]));
}

// ---------------- V transpose -> fp16 single: v[b][t][d] -> Vt[b][d][t-pairs] ----
#define VT_SMEM (256 * 69 * 4)
__global__ __launch_bounds__(256) void transpose_v_f16(
    const float* __restrict__ v, uint32_t* __restrict__ vth)
{
    extern __shared__ float st[];
    int b = blockIdx.y, t0 = blockIdx.x * 64;
    int tid = threadIdx.x;
    const float* vb = v + ((size_t)(b * T_SEQ + t0)) * HD;
#pragma unroll
    for (int i = 0; i < 16; i++) {
        int f = i * 256 + tid;
        int t = f >> 6, d4 = (f & 63) * 4;
        float4 x = *(const float4*)(vb + (size_t)t * HD + d4);
        st[(d4 + 0) * 69 + t] = x.x;
        st[(d4 + 1) * 69 + t] = x.y;
        st[(d4 + 2) * 69 + t] = x.z;
        st[(d4 + 3) * 69 + t] = x.w;
    }
    __syncthreads();
    int w = tid >> 5, l = tid & 31;
#pragma unroll
    for (int pass = 0; pass < 32; pass++) {
        int d = pass * 8 + w;
        float x0 = st[d * 69 + 2 * l];
        float x1 = st[d * 69 + 2 * l + 1];
        size_t o = ((size_t)(b * HD + d)) * (T_SEQ / 2) + (t0 >> 1) + l;
        vth[o] = pack2(to_f16(x0), to_f16(x1));
    }
}

// ==== sliding-window flash attention: 2-term fp16 (Q hi/lo · K hi; P hi/lo · V hi) ====
#define AQ_STR 132
#define AV_STR 36
#define OFF_QH   0
#define OFF_QL   (64 * AQ_STR)
#define OFF_KV   (2 * 64 * AQ_STR)          // K [64][132] (8448) or V^T [256][36] (9216)
#define OFF_PH   (OFF_KV + 9216)
#define OFF_PL   (OFF_PH + 64 * AV_STR)
#define OFF_RED  (OFF_PL + 64 * AV_STR)
#define OFF_RED2 (OFF_RED + 256)
#define OFF_MS   (OFF_RED2 + 256)
#define OFF_LS   (OFF_MS + 64)
#define ATTN_U32 (OFF_LS + 64)
#define ATTN_SMEM (ATTN_U32 * 4)            // ~125 KB

__global__ __launch_bounds__(256, 1) void attn_swa_mma(
    const uint32_t* __restrict__ Qph, const uint32_t* __restrict__ Qpl,
    const uint32_t* __restrict__ Kph,
    const uint32_t* __restrict__ Vth,
    uint32_t* __restrict__ Oh, uint32_t* __restrict__ Ol)
{
    extern __shared__ uint32_t s[];
    const uint32_t sb = smem_u32p(s);
    uint32_t* Ph   = s + OFF_PH;
    uint32_t* Pl   = s + OFF_PL;
    float* red     = (float*)(s + OFF_RED);
    float* red2    = (float*)(s + OFF_RED2);
    float* m_s     = (float*)(s + OFF_MS);
    float* l_s     = (float*)(s + OFF_LS);

    const int tid  = threadIdx.x;
    const int wid  = tid >> 5, lane = tid & 31, quad = lane >> 2, tq = lane & 3;
    const int wm   = wid & 1, wn = wid >> 1;
    const int jm   = lane >> 3, jr = lane & 7;
    const int a_ro = (jm & 1) * 8 + jr;
    const int a_ko = (jm >> 1) * 4;
    const int b_go = jm >> 1;
    const int b_ko = (jm & 1) * 4;
    const int qt   = blockIdx.x & 63;
    const int h    = (blockIdx.x >> 6) & 3;
    const int b    = blockIdx.x >> 8;
    const int q0   = qt << 6;

    const uint32_t* qh_g = Qph + ((size_t)(b * T_SEQ + q0)) * (CDIM / 2) + h * (HD / 2);
    const uint32_t* ql_g = Qpl + ((size_t)(b * T_SEQ + q0)) * (CDIM / 2) + h * (HD / 2);
    const uint32_t* kh_g = Kph + (size_t)b * T_SEQ * (HD / 2);
    const uint32_t* vh_g = Vth + (size_t)b * HD * (T_SEQ / 2);

    // ---- Q tile (hi + lo) ----
#pragma unroll
    for (int i = 0; i < 8; i++) {
        int f = i * 256 + tid, row = f >> 5, c4 = (f & 31) * 4;
        cpa16(sb + (uint32_t)(OFF_QH + row * AQ_STR + c4) * 4u, qh_g + (size_t)row * (CDIM / 2) + c4);
        cpa16(sb + (uint32_t)(OFF_QL + row * AQ_STR + c4) * 4u, ql_g + (size_t)row * (CDIM / 2) + c4);
    }
    CP_COMMIT();
    if (tid < 64) { m_s[tid] = -1e30f; l_s[tid] = 0.f; }
    CP_WAIT0();
    __syncthreads();

    float oacc[2][8][4];
#pragma unroll
    for (int mf = 0; mf < 2; mf++)
#pragma unroll
        for (int nf = 0; nf < 8; nf++)
#pragma unroll
            for (int r = 0; r < 4; r++) oacc[mf][nf][r] = 0.f;

    int kt0 = q0 - WIN; if (kt0 < 0) kt0 = 0;

    for (int kt = kt0; kt <= q0; kt += 64) {
        __syncthreads();   // A: prev PV done reading KV(V)/P

        // ---- K tile (hi only) ----
#pragma unroll
        for (int i = 0; i < 8; i++) {
            int f = i * 256 + tid, row = f >> 5, c4 = (f & 31) * 4;
            cpa16(sb + (uint32_t)(OFF_KV + row * AQ_STR + c4) * 4u, kh_g + (size_t)(kt + row) * (HD / 2) + c4);
        }
        CP_COMMIT();
        CP_WAIT0();
        __syncthreads();   // B

        // ---- S = (Qh+Ql) Kh^T ----
        float sacc[2][2][4];
#pragma unroll
        for (int mf = 0; mf < 2; mf++)
#pragma unroll
            for (int nf = 0; nf < 2; nf++)
#pragma unroll
                for (int r = 0; r < 4; r++) sacc[mf][nf][r] = 0.f;

#pragma unroll
        for (int ks = 0; ks < 16; ks++) {
            const int kb = ks * 8;
            uint32_t ah[2][4], al[2][4];
#pragma unroll
            for (int mf = 0; mf < 2; mf++) {
                uint32_t ar = sb + (uint32_t)(OFF_QH + (wm*32 + mf*16 + a_ro) * AQ_STR + kb + a_ko) * 4u;
                LDSM4(ah[mf][0], ah[mf][1], ah[mf][2], ah[mf][3], ar);
                LDSM4(al[mf][0], al[mf][1], al[mf][2], al[mf][3], ar + (OFF_QL - OFF_QH) * 4u);
            }
            uint32_t br = sb + (uint32_t)(OFF_KV + (wn*16 + b_go*8 + jr) * AQ_STR + kb + b_ko) * 4u;
            uint32_t b0h[2], b1h[2];
            LDSM4(b0h[0], b0h[1], b1h[0], b1h[1], br);
#pragma unroll
            for (int mf = 0; mf < 2; mf++) {
                MMA_F16(sacc[mf][0], ah[mf], b0h);
                MMA_F16(sacc[mf][0], al[mf], b0h);
                MMA_F16(sacc[mf][1], ah[mf], b1h);
                MMA_F16(sacc[mf][1], al[mf], b1h);
            }
        }

        // ---- mask + scale + row max ----
#pragma unroll
        for (int mf = 0; mf < 2; mf++)
#pragma unroll
            for (int half = 0; half < 2; half++) {
                int rowl = wm * 32 + mf * 16 + quad + half * 8;
                int irow = q0 + rowl;
                float mt = -1e30f;
#pragma unroll
                for (int nf = 0; nf < 2; nf++)
#pragma unroll
                    for (int p = 0; p < 2; p++) {
                        int j = kt + wn * 16 + nf * 8 + tq * 2 + p;
                        bool ok = (j <= irow) && (j >= irow - WIN);
                        float x = ok ? sacc[mf][nf][half * 2 + p] * 0.0625f : -1e30f;
                        sacc[mf][nf][half * 2 + p] = x;
                        mt = fmaxf(mt, x);
                    }
                mt = fmaxf(mt, __shfl_xor_sync(0xffffffffu, mt, 1));
                mt = fmaxf(mt, __shfl_xor_sync(0xffffffffu, mt, 2));
                if (tq == 0) red[wn * 64 + rowl] = mt;
            }
        __syncthreads();   // C

        // ---- V^T tile (hi only; overlaps softmax) ----
#pragma unroll
        for (int i = 0; i < 8; i++) {
            int f = i * 256 + tid, d = f >> 3, c4 = (f & 7) * 4;
            cpa16(sb + (uint32_t)(OFF_KV + d * AV_STR + c4) * 4u, vh_g + (size_t)d * (T_SEQ / 2) + (kt >> 1) + c4);
        }
        CP_COMMIT();

        float mn_loc[2][2], corr_loc[2][2];
#pragma unroll
        for (int mf = 0; mf < 2; mf++)
#pragma unroll
            for (int half = 0; half < 2; half++) {
                int rowl = wm * 32 + mf * 16 + quad + half * 8;
                float mt = fmaxf(fmaxf(red[rowl], red[64 + rowl]),
                                 fmaxf(red[128 + rowl], red[192 + rowl]));
                float mo = m_s[rowl];
                float mn = fmaxf(mo, mt);
                mn_loc[mf][half]   = mn;
                corr_loc[mf][half] = __expf(mo - mn);
            }

        // ---- P = exp(S - m); split fp16 -> Ph/Pl; row sums ----
#pragma unroll
        for (int mf = 0; mf < 2; mf++)
#pragma unroll
            for (int half = 0; half < 2; half++) {
                int rowl = wm * 32 + mf * 16 + quad + half * 8;
                float mn = mn_loc[mf][half];
                float rs = 0.f;
#pragma unroll
                for (int nf = 0; nf < 2; nf++) {
                    float p0 = __expf(sacc[mf][nf][half * 2 + 0] - mn);
                    float p1 = __expf(sacc[mf][nf][half * 2 + 1] - mn);
                    rs += p0 + p1;
                    uint16_t h0, l0, h1, l1;
                    split_f16(p0, h0, l0); split_f16(p1, h1, l1);
                    int o = rowl * AV_STR + wn * 8 + nf * 4 + tq;
                    Ph[o] = pack2(h0, h1);
                    Pl[o] = pack2(l0, l1);
                }
                rs += __shfl_xor_sync(0xffffffffu, rs, 1);
                rs += __shfl_xor_sync(0xffffffffu, rs, 2);
                if (tq == 0) red2[wn * 64 + rowl] = rs;
            }
        __syncthreads();   // E

        if (wid < 2 && tq == 0) {
#pragma unroll
            for (int mf = 0; mf < 2; mf++)
#pragma unroll
                for (int half = 0; half < 2; half++) {
                    int rowl = wid * 32 + mf * 16 + quad + half * 8;
                    l_s[rowl] = l_s[rowl] * corr_loc[mf][half] +
                                red2[rowl] + red2[64 + rowl] + red2[128 + rowl] + red2[192 + rowl];
                    m_s[rowl] = mn_loc[mf][half];
                }
        }
#pragma unroll
        for (int mf = 0; mf < 2; mf++) {
            float c0 = corr_loc[mf][0], c1 = corr_loc[mf][1];
#pragma unroll
            for (int nf = 0; nf < 8; nf++) {
                oacc[mf][nf][0] *= c0; oacc[mf][nf][1] *= c0;
                oacc[mf][nf][2] *= c1; oacc[mf][nf][3] *= c1;
            }
        }
        CP_WAIT0();
        __syncthreads();   // F

        // ---- O += (Ph+Pl) Vh ----
#pragma unroll
        for (int kk = 0; kk < 4; kk++) {
            const int kb = kk * 8;
            uint32_t pah[2][4], pal[2][4];
#pragma unroll
            for (int mf = 0; mf < 2; mf++) {
                uint32_t ar = sb + (uint32_t)(OFF_PH + (wm*32 + mf*16 + a_ro) * AV_STR + kb + a_ko) * 4u;
                LDSM4(pah[mf][0], pah[mf][1], pah[mf][2], pah[mf][3], ar);
                LDSM4(pal[mf][0], pal[mf][1], pal[mf][2], pal[mf][3], ar + (OFF_PL - OFF_PH) * 4u);
            }
#pragma unroll
            for (int g = 0; g < 4; g++) {
                uint32_t br = sb + (uint32_t)(OFF_KV + (wn*64 + (2*g + b_go)*8 + jr) * AV_STR + kb + b_ko) * 4u;
                uint32_t v0h[2], v1h[2];
                LDSM4(v0h[0], v0h[1], v1h[0], v1h[1], br);
#pragma unroll
                for (int mf = 0; mf < 2; mf++) {
                    MMA_F16(oacc[mf][2*g],   pah[mf], v0h);
                    MMA_F16(oacc[mf][2*g],   pal[mf], v0h);
                    MMA_F16(oacc[mf][2*g+1], pah[mf], v1h);
                    MMA_F16(oacc[mf][2*g+1], pal[mf], v1h);
                }
            }
        }
    }

    // ---- epilogue: write ao directly as packed f16x2 hi/lo (Wo GEMM operand) ----
#pragma unroll
    for (int mf = 0; mf < 2; mf++) {
        int r0 = wm * 32 + mf * 16 + quad;
        float i0 = 1.f / l_s[r0], i1 = 1.f / l_s[r0 + 8];
        size_t base0 = ((size_t)(b * T_SEQ + q0 + r0)) * (CDIM / 2) + h * (HD / 2);
        size_t base1 = base0 + 8 * (CDIM / 2);
#pragma unroll
        for (int nf = 0; nf < 8; nf++) {
            int cp_ = wn * 32 + nf * 4 + tq;
            uint16_t h0, l0, h1, l1;
            split_f16(oacc[mf][nf][0] * i0, h0, l0);
            split_f16(oacc[mf][nf][1] * i0, h1, l1);
            Oh[base0 + cp_] = pack2(h0, h1);
            Ol[base0 + cp_] = pack2(l0, l1);
            split_f16(oacc[mf][nf][2] * i1, h0, l0);
            split_f16(oacc[mf][nf][3] * i1, h1, l1);
            Oh[base1 + cp_] = pack2(h0, h1);
            Ol[base1 + cp_] = pack2(l0, l1);
        }
    }
}

// ---------------- launch ----------------
extern "C" void kernel_launch(void* const* d_in, const int* in_sizes, int n_in,
                              void* d_out, int out_size)
{
    const float* x  = (const float*)d_in[0];
    const float* Wq = (const float*)d_in[1];
    const float* Wk = (const float*)d_in[2];
    const float* Wv = (const float*)d_in[3];
    const float* Wo = (const float*)d_in[4];
    const float* qg = (const float*)d_in[5];
    const float* kg = (const float*)d_in[6];
    float* out = (float*)d_out;

    float *q, *k, *v;
    uint32_t *xh, *xl, *aoh, *aol, *wqh, *wql, *wkh, *wkl, *wvh, *wvl, *woh, *wol;
    uint32_t *qph, *qpl, *kph, *kpl, *vth;
    cudaGetSymbolAddress((void**)&q,   g_q);
    cudaGetSymbolAddress((void**)&k,   g_k);
    cudaGetSymbolAddress((void**)&v,   g_v);
    cudaGetSymbolAddress((void**)&xh,  g_xh);
    cudaGetSymbolAddress((void**)&xl,  g_xl);
    cudaGetSymbolAddress((void**)&aoh, g_aoh);
    cudaGetSymbolAddress((void**)&aol, g_aol);
    cudaGetSymbolAddress((void**)&wqh, g_wqh);
    cudaGetSymbolAddress((void**)&wql, g_wql);
    cudaGetSymbolAddress((void**)&wkh, g_wkh);
    cudaGetSymbolAddress((void**)&wkl, g_wkl);
    cudaGetSymbolAddress((void**)&wvh, g_wvh);
    cudaGetSymbolAddress((void**)&wvl, g_wvl);
    cudaGetSymbolAddress((void**)&woh, g_woh);
    cudaGetSymbolAddress((void**)&wol, g_wol);
    cudaGetSymbolAddress((void**)&qph, g_qph);
    cudaGetSymbolAddress((void**)&qpl, g_qpl);
    cudaGetSymbolAddress((void**)&kph, g_kph);
    cudaGetSymbolAddress((void**)&kpl, g_kpl);
    cudaGetSymbolAddress((void**)&vth, g_vth);

    const int M = BATCH * T_SEQ;   // 8192

    init_invf<<<1, 128>>>();

    split_pack_f16<<<(M * CDIM / 8 + 255) / 256, 256>>>(x,  xh,  xl,  M * CDIM / 8);
    split_pack_f16<<<(CDIM * CDIM / 8 + 255) / 256, 256>>>(Wq, wqh, wql, CDIM * CDIM / 8);
    split_pack_f16<<<(HD * CDIM / 8 + 255) / 256, 256>>>(Wk, wkh, wkl, HD * CDIM / 8);
    split_pack_f16<<<(HD * CDIM / 8 + 255) / 256, 256>>>(Wv, wvh, wvl, HD * CDIM / 8);
    split_pack_f16<<<(CDIM * CDIM / 8 + 255) / 256, 256>>>(Wo, woh, wol, CDIM * CDIM / 8);

    cudaFuncSetAttribute(gemm_f16_2t, cudaFuncAttributeMaxDynamicSharedMemorySize, GEMM_SMEM);

    // fused Q+K+V projection
    gemm_f16_2t<<<dim3(12, M / 128), 256, GEMM_SMEM>>>(
        M, CDIM, 8, 10, xh, xl,
        wqh, q, CDIM,
        wkh, k, HD,
        wvh, v, HD);

    rmsnorm_rope_pack<<<(M * NH) / 8, 256>>>(q, qg, qph, qpl, M * NH, NH);
    rmsnorm_rope_pack<<<M / 8, 256>>>(k, kg, kph, kpl, M, 1);

    cudaFuncSetAttribute(transpose_v_f16, cudaFuncAttributeMaxDynamicSharedMemorySize, VT_SMEM);
    transpose_v_f16<<<dim3(T_SEQ / 64, BATCH), 256, VT_SMEM>>>(v, vth);

    cudaFuncSetAttribute(attn_swa_mma, cudaFuncAttributeMaxDynamicSharedMemorySize, ATTN_SMEM);
    attn_swa_mma<<<BATCH * NH * (T_SEQ / 64), 256, ATTN_SMEM>>>(
        qph, qpl, kph, vth, aoh, aol);

    // output projection
    gemm_f16_2t<<<dim3(8, M / 128), 256, GEMM_SMEM>>>(
        M, CDIM, 8, 8, aoh, aol,
        woh, out, CDIM,
        woh, out, CDIM,
        woh, out, CDIM);
}

// round 14
// speedup vs baseline: 3.2471x; 1.1453x over previous
#include <cuda_runtime.h>
#include <math.h>
#include <stdint.h>

#define T_SEQ 4096
#define BATCH 2
#define CDIM  1024
#define HD    256
#define NH    4
#define WIN   512

// ---------------- scratch (static device globals; no allocation) ----------------
__device__ float    g_q [(size_t)BATCH * T_SEQ * CDIM];
__device__ float    g_k [(size_t)BATCH * T_SEQ * HD];
__device__ float    g_v [(size_t)BATCH * T_SEQ * HD];
__device__ float    g_invf[HD / 2];
// packed f16x2 operand buffers
__device__ uint32_t g_xh [(size_t)BATCH * T_SEQ * CDIM / 2];
__device__ uint32_t g_xl [(size_t)BATCH * T_SEQ * CDIM / 2];
__device__ uint32_t g_aoh[(size_t)BATCH * T_SEQ * CDIM / 2];
__device__ uint32_t g_aol[(size_t)BATCH * T_SEQ * CDIM / 2];
__device__ uint32_t g_wqh[CDIM * CDIM / 2];
__device__ uint32_t g_wkh[HD * CDIM / 2];
__device__ uint32_t g_wvh[HD * CDIM / 2];
__device__ uint32_t g_woh[CDIM * CDIM / 2];
// attention operands (all single fp16 except ao)
__device__ uint32_t g_qph[(size_t)BATCH * T_SEQ * CDIM / 2];
__device__ uint32_t g_kph[(size_t)BATCH * T_SEQ * HD / 2];
__device__ uint32_t g_vth[(size_t)BATCH * HD * T_SEQ / 2];

// ---------------- common helpers ----------------
__device__ __forceinline__ void split_f16(float x, uint16_t& h, uint16_t& l) {
    asm("cvt.rn.f16.f32 %0, %1;" : "=h"(h) : "f"(x));
    float hf;
    asm("cvt.f32.f16 %0, %1;" : "=f"(hf) : "h"(h));
    float r = x - hf;                       // exact
    asm("cvt.rn.f16.f32 %0, %1;" : "=h"(l) : "f"(r));
}
__device__ __forceinline__ uint16_t to_f16(float x) {
    uint16_t h;
    asm("cvt.rn.f16.f32 %0, %1;" : "=h"(h) : "f"(x));
    return h;
}
__device__ __forceinline__ uint32_t pack2(uint16_t a, uint16_t b) {
    return (uint32_t)a | ((uint32_t)b << 16);
}
__device__ __forceinline__ uint32_t smem_u32p(const void* p) {
    uint32_t a;
    asm("{ .reg .u64 t; cvta.to.shared.u64 t, %1; cvt.u32.u64 %0, t; }" : "=r"(a) : "l"(p));
    return a;
}

#define MMA_F16(d, a, b) \
    asm volatile("mma.sync.aligned.m16n8k16.row.col.f32.f16.f16.f32 " \
        "{%0,%1,%2,%3}, {%4,%5,%6,%7}, {%8,%9}, {%0,%1,%2,%3};" \
        : "+f"((d)[0]), "+f"((d)[1]), "+f"((d)[2]), "+f"((d)[3]) \
        : "r"((a)[0]), "r"((a)[1]), "r"((a)[2]), "r"((a)[3]), \
          "r"((b)[0]), "r"((b)[1]))

#define LDSM4(r0, r1, r2, r3, a) \
    asm volatile("ldmatrix.sync.aligned.m8n8.x4.shared.b16 {%0,%1,%2,%3}, [%4];" \
        : "=r"(r0), "=r"(r1), "=r"(r2), "=r"(r3) : "r"(a))

__device__ __forceinline__ void cpa16(uint32_t sa, const void* ga) {
    asm volatile("cp.async.cg.shared.global [%0], [%1], 16;" :: "r"(sa), "l"(ga));
}
#define CP_COMMIT() asm volatile("cp.async.commit_group;" ::: "memory")
#define CP_WAIT0()  asm volatile("cp.async.wait_group 0;" ::: "memory")

// ============ fused preprocessing: invf + x split(hi,lo) + weights (hi) ============
// block segments: [0,4096) x | [4096,4608) Wq | [4608,4736) Wk | [4736,4864) Wv | [4864,5376) Wo
#define PREP_BLOCKS 5376
__global__ __launch_bounds__(256) void prep_all(
    const float* __restrict__ x,  const float* __restrict__ Wq,
    const float* __restrict__ Wk, const float* __restrict__ Wv,
    const float* __restrict__ Wo,
    uint32_t* __restrict__ xh, uint32_t* __restrict__ xl,
    uint32_t* __restrict__ wqh, uint32_t* __restrict__ wkh,
    uint32_t* __restrict__ wvh, uint32_t* __restrict__ woh)
{
    const int bid = blockIdx.x;
    const int tid = threadIdx.x;
    if (bid == 0 && tid < 128) {
        float e = (float)(2 * tid) * (1.0f / HD);
        g_invf[tid] = (float)pow(1000000.0, -(double)e);
    }
    const float* in; uint32_t* oh; int i; bool with_lo = false; uint32_t* ol = 0;
    if (bid < 4096)      { in = x;  oh = xh;  ol = xl; with_lo = true; i = bid * 256 + tid; }
    else if (bid < 4608) { in = Wq; oh = wqh; i = (bid - 4096) * 256 + tid; }
    else if (bid < 4736) { in = Wk; oh = wkh; i = (bid - 4608) * 256 + tid; }
    else if (bid < 4864) { in = Wv; oh = wvh; i = (bid - 4736) * 256 + tid; }
    else                 { in = Wo; oh = woh; i = (bid - 4864) * 256 + tid; }

    float4 a = ((const float4*)in)[2 * i];
    float4 b = ((const float4*)in)[2 * i + 1];
    uint16_t h[8], l[8];
    split_f16(a.x, h[0], l[0]); split_f16(a.y, h[1], l[1]);
    split_f16(a.z, h[2], l[2]); split_f16(a.w, h[3], l[3]);
    split_f16(b.x, h[4], l[4]); split_f16(b.y, h[5], l[5]);
    split_f16(b.z, h[6], l[6]); split_f16(b.w, h[7], l[7]);
    ((uint4*)oh)[i] = make_uint4(pack2(h[0],h[1]), pack2(h[2],h[3]), pack2(h[4],h[5]), pack2(h[6],h[7]));
    if (with_lo)
        ((uint4*)ol)[i] = make_uint4(pack2(l[0],l[1]), pack2(l[2],l[3]), pack2(l[4],l[5]), pack2(l[6],l[7]));
}

// ===== 2-term fp16 GEMM: C = (Ah+Al)·Bh^T, multi-segment N (fused QKV) =====
#define STRP 20
#define PART_U32 (128 * STRP)               // 2560
#define BUF_U32  (3 * PART_U32)             // Ah, Al, Bh
#define GEMM_SMEM (2 * BUF_U32 * 4)         // 61440 B

__global__ __launch_bounds__(256, 2) void gemm_f16_2t(
    int M, int K, int tiles0, int tiles01,
    const uint32_t* __restrict__ Ah, const uint32_t* __restrict__ Al,
    const uint32_t* __restrict__ Bh0, float* __restrict__ C0, int N0,
    const uint32_t* __restrict__ Bh1, float* __restrict__ C1, int N1,
    const uint32_t* __restrict__ Bh2, float* __restrict__ C2, int N2)
{
    extern __shared__ uint32_t s32[];
    const uint32_t sb = smem_u32p(s32);

    const int nt = blockIdx.x;
    const uint32_t* Bh; float* C; int N, ntl;
    if (nt < tiles0)       { Bh = Bh0; C = C0; N = N0; ntl = nt; }
    else if (nt < tiles01) { Bh = Bh1; C = C1; N = N1; ntl = nt - tiles0; }
    else                   { Bh = Bh2; C = C2; N = N2; ntl = nt - tiles01; }

    const int tid    = threadIdx.x;
    const int wid    = tid >> 5;
    const int lane   = tid & 31;
    const int quad   = lane >> 2;
    const int tq     = lane & 3;
    const int warp_m = wid & 3;
    const int warp_n = wid >> 2;
    const int m0 = blockIdx.y << 7;
    const int n0 = ntl << 7;
    const int K2 = K >> 1;

    const int jm   = lane >> 3, jr = lane & 7;
    const int a_ro = (jm & 1) * 8 + jr;
    const int a_ko = (jm >> 1) * 4;
    const int b_go = jm >> 1;
    const int b_ko = (jm & 1) * 4;

    const uint32_t* pAh = Ah + (size_t)m0 * K2;
    const uint32_t* pAl = Al + (size_t)m0 * K2;
    const uint32_t* pBh = Bh + (size_t)n0 * K2;

    const int r0_ = tid >> 2;
    const int r1_ = 64 + r0_;
    const int qd  = (tid & 3) * 4;

#define LOADP(it, buf) do { \
    int kp = (it) * 16; \
    uint32_t sbase = sb + (uint32_t)(buf) * BUF_U32 * 4u; \
    cpa16(sbase + (uint32_t)(0*PART_U32 + r0_*STRP + qd)*4u, pAh + (size_t)r0_*K2 + kp + qd); \
    cpa16(sbase + (uint32_t)(0*PART_U32 + r1_*STRP + qd)*4u, pAh + (size_t)r1_*K2 + kp + qd); \
    cpa16(sbase + (uint32_t)(1*PART_U32 + r0_*STRP + qd)*4u, pAl + (size_t)r0_*K2 + kp + qd); \
    cpa16(sbase + (uint32_t)(1*PART_U32 + r1_*STRP + qd)*4u, pAl + (size_t)r1_*K2 + kp + qd); \
    cpa16(sbase + (uint32_t)(2*PART_U32 + r0_*STRP + qd)*4u, pBh + (size_t)r0_*K2 + kp + qd); \
    cpa16(sbase + (uint32_t)(2*PART_U32 + r1_*STRP + qd)*4u, pBh + (size_t)r1_*K2 + kp + qd); \
    CP_COMMIT(); \
} while (0)

    float acc[2][8][4];
#pragma unroll
    for (int mf = 0; mf < 2; mf++)
#pragma unroll
        for (int nf = 0; nf < 8; nf++)
#pragma unroll
            for (int r = 0; r < 4; r++) acc[mf][nf][r] = 0.f;

    const int NT = K / 32;

    LOADP(0, 0);

    for (int it = 0; it < NT; ++it) {
        CP_WAIT0();
        __syncthreads();
        if (it + 1 < NT) LOADP(it + 1, (it + 1) & 1);

        const uint32_t sA = sb + (uint32_t)(it & 1) * BUF_U32 * 4u;
        const uint32_t sB = sA + 2u * PART_U32 * 4u;

#pragma unroll
        for (int ks = 0; ks < 2; ks++) {
            const int kb = ks * 8;
            uint32_t ah[2][4], al[2][4];
#pragma unroll
            for (int mf = 0; mf < 2; mf++) {
                uint32_t ar = sA + (uint32_t)((warp_m*32 + mf*16 + a_ro) * STRP + kb + a_ko) * 4u;
                LDSM4(ah[mf][0], ah[mf][1], ah[mf][2], ah[mf][3], ar);
                LDSM4(al[mf][0], al[mf][1], al[mf][2], al[mf][3], ar + PART_U32*4u);
            }
#pragma unroll
            for (int g = 0; g < 4; g++) {
                uint32_t br = sB + (uint32_t)((warp_n*64 + (2*g + b_go)*8 + jr) * STRP + kb + b_ko) * 4u;
                uint32_t b0h[2], b1h[2];
                LDSM4(b0h[0], b0h[1], b1h[0], b1h[1], br);
#pragma unroll
                for (int mf = 0; mf < 2; mf++) {
                    MMA_F16(acc[mf][2*g],   ah[mf], b0h);
                    MMA_F16(acc[mf][2*g],   al[mf], b0h);
                    MMA_F16(acc[mf][2*g+1], ah[mf], b1h);
                    MMA_F16(acc[mf][2*g+1], al[mf], b1h);
                }
            }
        }
    }

#pragma unroll
    for (int mf = 0; mf < 2; mf++) {
        int row = m0 + warp_m * 32 + mf * 16 + quad;
#pragma unroll
        for (int nf = 0; nf < 8; nf++) {
            int col = n0 + warp_n * 64 + nf * 8 + tq * 2;
            *(float2*)(C + (size_t)row * N + col)       = make_float2(acc[mf][nf][0], acc[mf][nf][1]);
            *(float2*)(C + (size_t)(row + 8) * N + col) = make_float2(acc[mf][nf][2], acc[mf][nf][3]);
        }
    }
#undef LOADP
}

// ---------------- fused RMSNorm + RoPE (q + k in one launch) -> packed fp16 hi ----
__global__ void rmsnorm_rope_fused(const float* __restrict__ qin, const float* __restrict__ kin,
                                   const float* __restrict__ qg, const float* __restrict__ kg,
                                   uint32_t* __restrict__ qo, uint32_t* __restrict__ ko)
{
    const int NQ = BATCH * T_SEQ * NH;
    int gw   = (int)((blockIdx.x * blockDim.x + threadIdx.x) >> 5);
    int lane = threadIdx.x & 31;

    const float* in; const float* gamma; uint32_t* outp; int t;
    if (gw < NQ) {
        in = qin + (size_t)gw * HD; gamma = qg; outp = qo + (size_t)gw * (HD / 2);
        t = (gw >> 2) & (T_SEQ - 1);                 // gw = bt*NH + h
    } else {
        int r = gw - NQ;                             // 0 .. BATCH*T_SEQ-1
        in = kin + (size_t)r * HD; gamma = kg; outp = ko + (size_t)r * (HD / 2);
        t = r & (T_SEQ - 1);
    }

    float v[8];
    *(float4*)&v[0] = *(const float4*)(in + lane * 8);
    *(float4*)&v[4] = *(const float4*)(in + lane * 8 + 4);

    float ss = 0.f;
#pragma unroll
    for (int i = 0; i < 8; i++) ss += v[i] * v[i];
#pragma unroll
    for (int o = 16; o > 0; o >>= 1) ss += __shfl_xor_sync(0xffffffffu, ss, o);

    float r = rsqrtf(ss * (1.0f / HD) + 1e-6f);

    float g[8];
    *(float4*)&g[0] = *(const float4*)(gamma + lane * 8);
    *(float4*)&g[4] = *(const float4*)(gamma + lane * 8 + 4);

    float invf[4];
    *(float4*)invf = *(const float4*)(g_invf + lane * 4);

    float tf = (float)t;
#pragma unroll
    for (int p = 0; p < 4; p++) {
        float ang = tf * invf[p];
        float c, s;
        sincosf(ang, &s, &c);
        float x0 = v[2 * p]     * r * g[2 * p];
        float x1 = v[2 * p + 1] * r * g[2 * p + 1];
        v[2 * p]     = x0 * c - x1 * s;
        v[2 * p + 1] = x0 * s + x1 * c;
    }

    *(uint4*)(outp + lane * 4) = make_uint4(
        pack2(to_f16(v[0]), to_f16(v[1])), pack2(to_f16(v[2]), to_f16(v[3])),
        pack2(to_f16(v[4]), to_f16(v[5])), pack2(to_f16(v[6]), to_f16(v[7])));
}

// ---------------- V transpose -> fp16: v[b][t][d] -> Vt[b][d][t-pairs] ----------
#define VT_SMEM (256 * 69 * 4)
__global__ __launch_bounds__(256) void transpose_v_f16(
    const float* __restrict__ v, uint32_t* __restrict__ vth)
{
    extern __shared__ float st[];
    int b = blockIdx.y, t0 = blockIdx.x * 64;
    int tid = threadIdx.x;
    const float* vb = v + ((size_t)(b * T_SEQ + t0)) * HD;
#pragma unroll
    for (int i = 0; i < 16; i++) {
        int f = i * 256 + tid;
        int t = f >> 6, d4 = (f & 63) * 4;
        float4 x = *(const float4*)(vb + (size_t)t * HD + d4);
        st[(d4 + 0) * 69 + t] = x.x;
        st[(d4 + 1) * 69 + t] = x.y;
        st[(d4 + 2) * 69 + t] = x.z;
        st[(d4 + 3) * 69 + t] = x.w;
    }
    __syncthreads();
    int w = tid >> 5, l = tid & 31;
#pragma unroll
    for (int pass = 0; pass < 32; pass++) {
        int d = pass * 8 + w;
        float x0 = st[d * 69 + 2 * l];
        float x1 = st[d * 69 + 2 * l + 1];
        size_t o = ((size_t)(b * HD + d)) * (T_SEQ / 2) + (t0 >> 1) + l;
        vth[o] = pack2(to_f16(x0), to_f16(x1));
    }
}

// ==== sliding-window flash attention: fp16 Q,K,V single; P 2-term; occupancy 2 ====
#define AQ_STR 132
#define AV_STR 36
#define OFF_Q    0
#define OFF_KV   (64 * AQ_STR)              // 8448: K [64][132] or V^T [256][36]
#define OFF_PH   (OFF_KV + 9216)
#define OFF_PL   (OFF_PH + 64 * AV_STR)
#define OFF_RED  (OFF_PL + 64 * AV_STR)
#define OFF_RED2 (OFF_RED + 256)
#define OFF_MS   (OFF_RED2 + 256)
#define OFF_LS   (OFF_MS + 64)
#define ATTN_U32 (OFF_LS + 64)
#define ATTN_SMEM (ATTN_U32 * 4)            // 91648 B -> 2 CTAs/SM

__global__ __launch_bounds__(256, 2) void attn_swa_mma(
    const uint32_t* __restrict__ Qph,
    const uint32_t* __restrict__ Kph,
    const uint32_t* __restrict__ Vth,
    uint32_t* __restrict__ Oh, uint32_t* __restrict__ Ol)
{
    extern __shared__ uint32_t s[];
    const uint32_t sb = smem_u32p(s);
    uint32_t* Ph   = s + OFF_PH;
    uint32_t* Pl   = s + OFF_PL;
    float* red     = (float*)(s + OFF_RED);
    float* red2    = (float*)(s + OFF_RED2);
    float* m_s     = (float*)(s + OFF_MS);
    float* l_s     = (float*)(s + OFF_LS);

    const int tid  = threadIdx.x;
    const int wid  = tid >> 5, lane = tid & 31, quad = lane >> 2, tq = lane & 3;
    const int wm   = wid & 1, wn = wid >> 1;
    const int jm   = lane >> 3, jr = lane & 7;
    const int a_ro = (jm & 1) * 8 + jr;
    const int a_ko = (jm >> 1) * 4;
    const int b_go = jm >> 1;
    const int b_ko = (jm & 1) * 4;
    const int qt   = blockIdx.x & 63;
    const int h    = (blockIdx.x >> 6) & 3;
    const int b    = blockIdx.x >> 8;
    const int q0   = qt << 6;

    const uint32_t* qh_g = Qph + ((size_t)(b * T_SEQ + q0)) * (CDIM / 2) + h * (HD / 2);
    const uint32_t* kh_g = Kph + (size_t)b * T_SEQ * (HD / 2);
    const uint32_t* vh_g = Vth + (size_t)b * HD * (T_SEQ / 2);

    // ---- Q tile (single fp16) ----
#pragma unroll
    for (int i = 0; i < 8; i++) {
        int f = i * 256 + tid, row = f >> 5, c4 = (f & 31) * 4;
        cpa16(sb + (uint32_t)(OFF_Q + row * AQ_STR + c4) * 4u, qh_g + (size_t)row * (CDIM / 2) + c4);
    }
    CP_COMMIT();
    if (tid < 64) { m_s[tid] = -1e30f; l_s[tid] = 0.f; }
    CP_WAIT0();
    __syncthreads();

    float oacc[2][8][4];
#pragma unroll
    for (int mf = 0; mf < 2; mf++)
#pragma unroll
        for (int nf = 0; nf < 8; nf++)
#pragma unroll
            for (int r = 0; r < 4; r++) oacc[mf][nf][r] = 0.f;

    int kt0 = q0 - WIN; if (kt0 < 0) kt0 = 0;

    for (int kt = kt0; kt <= q0; kt += 64) {
        __syncthreads();   // A: prev PV done reading KV(V)/P

        // ---- K tile ----
#pragma unroll
        for (int i = 0; i < 8; i++) {
            int f = i * 256 + tid, row = f >> 5, c4 = (f & 31) * 4;
            cpa16(sb + (uint32_t)(OFF_KV + row * AQ_STR + c4) * 4u, kh_g + (size_t)(kt + row) * (HD / 2) + c4);
        }
        CP_COMMIT();
        CP_WAIT0();
        __syncthreads();   // B

        // ---- S = Qh Kh^T ----
        float sacc[2][2][4];
#pragma unroll
        for (int mf = 0; mf < 2; mf++)
#pragma unroll
            for (int nf = 0; nf < 2; nf++)
#pragma unroll
                for (int r = 0; r < 4; r++) sacc[mf][nf][r] = 0.f;

#pragma unroll
        for (int ks = 0; ks < 16; ks++) {
            const int kb = ks * 8;
            uint32_t ah[2][4];
#pragma unroll
            for (int mf = 0; mf < 2; mf++) {
                uint32_t ar = sb + (uint32_t)(OFF_Q + (wm*32 + mf*16 + a_ro) * AQ_STR + kb + a_ko) * 4u;
                LDSM4(ah[mf][0], ah[mf][1], ah[mf][2], ah[mf][3], ar);
            }
            uint32_t br = sb + (uint32_t)(OFF_KV + (wn*16 + b_go*8 + jr) * AQ_STR + kb + b_ko) * 4u;
            uint32_t b0h[2], b1h[2];
            LDSM4(b0h[0], b0h[1], b1h[0], b1h[1], br);
#pragma unroll
            for (int mf = 0; mf < 2; mf++) {
                MMA_F16(sacc[mf][0], ah[mf], b0h);
                MMA_F16(sacc[mf][1], ah[mf], b1h);
            }
        }

        // ---- mask + scale + row max ----
#pragma unroll
        for (int mf = 0; mf < 2; mf++)
#pragma unroll
            for (int half = 0; half < 2; half++) {
                int rowl = wm * 32 + mf * 16 + quad + half * 8;
                int irow = q0 + rowl;
                float mt = -1e30f;
#pragma unroll
                for (int nf = 0; nf < 2; nf++)
#pragma unroll
                    for (int p = 0; p < 2; p++) {
                        int j = kt + wn * 16 + nf * 8 + tq * 2 + p;
                        bool ok = (j <= irow) && (j >= irow - WIN);
                        float x = ok ? sacc[mf][nf][half * 2 + p] * 0.0625f : -1e30f;
                        sacc[mf][nf][half * 2 + p] = x;
                        mt = fmaxf(mt, x);
                    }
                mt = fmaxf(mt, __shfl_xor_sync(0xffffffffu, mt, 1));
                mt = fmaxf(mt, __shfl_xor_sync(0xffffffffu, mt, 2));
                if (tq == 0) red[wn * 64 + rowl] = mt;
            }
        __syncthreads();   // C

        // ---- V^T tile (overlaps softmax) ----
#pragma unroll
        for (int i = 0; i < 8; i++) {
            int f = i * 256 + tid, d = f >> 3, c4 = (f & 7) * 4;
            cpa16(sb + (uint32_t)(OFF_KV + d * AV_STR + c4) * 4u, vh_g + (size_t)d * (T_SEQ / 2) + (kt >> 1) + c4);
        }
        CP_COMMIT();

        float mn_loc[2][2], corr_loc[2][2];
#pragma unroll
        for (int mf = 0; mf < 2; mf++)
#pragma unroll
            for (int half = 0; half < 2; half++) {
                int rowl = wm * 32 + mf * 16 + quad + half * 8;
                float mt = fmaxf(fmaxf(red[rowl], red[64 + rowl]),
                                 fmaxf(red[128 + rowl], red[192 + rowl]));
                float mo = m_s[rowl];
                float mn = fmaxf(mo, mt);
                mn_loc[mf][half]   = mn;
                corr_loc[mf][half] = __expf(mo - mn);
            }

        // ---- P = exp(S - m); split fp16 -> Ph/Pl; row sums ----
#pragma unroll
        for (int mf = 0; mf < 2; mf++)
#pragma unroll
            for (int half = 0; half < 2; half++) {
                int rowl = wm * 32 + mf * 16 + quad + half * 8;
                float mn = mn_loc[mf][half];
                float rs = 0.f;
#pragma unroll
                for (int nf = 0; nf < 2; nf++) {
                    float p0 = __expf(sacc[mf][nf][half * 2 + 0] - mn);
                    float p1 = __expf(sacc[mf][nf][half * 2 + 1] - mn);
                    rs += p0 + p1;
                    uint16_t h0, l0, h1, l1;
                    split_f16(p0, h0, l0); split_f16(p1, h1, l1);
                    int o = rowl * AV_STR + wn * 8 + nf * 4 + tq;
                    Ph[o] = pack2(h0, h1);
                    Pl[o] = pack2(l0, l1);
                }
                rs += __shfl_xor_sync(0xffffffffu, rs, 1);
                rs += __shfl_xor_sync(0xffffffffu, rs, 2);
                if (tq == 0) red2[wn * 64 + rowl] = rs;
            }
        __syncthreads();   // E

        if (wid < 2 && tq == 0) {
#pragma unroll
            for (int mf = 0; mf < 2; mf++)
#pragma unroll
                for (int half = 0; half < 2; half++) {
                    int rowl = wid * 32 + mf * 16 + quad + half * 8;
                    l_s[rowl] = l_s[rowl] * corr_loc[mf][half] +
                                red2[rowl] + red2[64 + rowl] + red2[128 + rowl] + red2[192 + rowl];
                    m_s[rowl] = mn_loc[mf][half];
                }
        }
#pragma unroll
        for (int mf = 0; mf < 2; mf++) {
            float c0 = corr_loc[mf][0], c1 = corr_loc[mf][1];
#pragma unroll
            for (int nf = 0; nf < 8; nf++) {
                oacc[mf][nf][0] *= c0; oacc[mf][nf][1] *= c0;
                oacc[mf][nf][2] *= c1; oacc[mf][nf][3] *= c1;
            }
        }
        CP_WAIT0();
        __syncthreads();   // F

        // ---- O += (Ph+Pl) Vh ----
#pragma unroll
        for (int kk = 0; kk < 4; kk++) {
            const int kb = kk * 8;
            uint32_t pah[2][4], pal[2][4];
#pragma unroll
            for (int mf = 0; mf < 2; mf++) {
                uint32_t ar = sb + (uint32_t)(OFF_PH + (wm*32 + mf*16 + a_ro) * AV_STR + kb + a_ko) * 4u;
                LDSM4(pah[mf][0], pah[mf][1], pah[mf][2], pah[mf][3], ar);
                LDSM4(pal[mf][0], pal[mf][1], pal[mf][2], pal[mf][3], ar + (OFF_PL - OFF_PH) * 4u);
            }
#pragma unroll
            for (int g = 0; g < 4; g++) {
                uint32_t br = sb + (uint32_t)(OFF_KV + (wn*64 + (2*g + b_go)*8 + jr) * AV_STR + kb + b_ko) * 4u;
                uint32_t v0h[2], v1h[2];
                LDSM4(v0h[0], v0h[1], v1h[0], v1h[1], br);
#pragma unroll
                for (int mf = 0; mf < 2; mf++) {
                    MMA_F16(oacc[mf][2*g],   pah[mf], v0h);
                    MMA_F16(oacc[mf][2*g],   pal[mf], v0h);
                    MMA_F16(oacc[mf][2*g+1], pah[mf], v1h);
                    MMA_F16(oacc[mf][2*g+1], pal[mf], v1h);
                }
            }
        }
    }

    // ---- epilogue: write ao as packed f16x2 hi/lo (Wo GEMM operand) ----
#pragma unroll
    for (int mf = 0; mf < 2; mf++) {
        int r0 = wm * 32 + mf * 16 + quad;
        float i0 = 1.f / l_s[r0], i1 = 1.f / l_s[r0 + 8];
        size_t base0 = ((size_t)(b * T_SEQ + q0 + r0)) * (CDIM / 2) + h * (HD / 2);
        size_t base1 = base0 + 8 * (CDIM / 2);
#pragma unroll
        for (int nf = 0; nf < 8; nf++) {
            int cp_ = wn * 32 + nf * 4 + tq;
            uint16_t h0, l0, h1, l1;
            split_f16(oacc[mf][nf][0] * i0, h0, l0);
            split_f16(oacc[mf][nf][1] * i0, h1, l1);
            Oh[base0 + cp_] = pack2(h0, h1);
            Ol[base0 + cp_] = pack2(l0, l1);
            split_f16(oacc[mf][nf][2] * i1, h0, l0);
            split_f16(oacc[mf][nf][3] * i1, h1, l1);
            Oh[base1 + cp_] = pack2(h0, h1);
            Ol[base1 + cp_] = pack2(l0, l1);
        }
    }
}

// ---------------- launch ----------------
extern "C" void kernel_launch(void* const* d_in, const int* in_sizes, int n_in,
                              void* d_out, int out_size)
{
    const float* x  = (const float*)d_in[0];
    const float* Wq = (const float*)d_in[1];
    const float* Wk = (const float*)d_in[2];
    const float* Wv = (const float*)d_in[3];
    const float* Wo = (const float*)d_in[4];
    const float* qg = (const float*)d_in[5];
    const float* kg = (const float*)d_in[6];
    float* out = (float*)d_out;

    float *q, *k, *v;
    uint32_t *xh, *xl, *aoh, *aol, *wqh, *wkh, *wvh, *woh;
    uint32_t *qph, *kph, *vth;
    cudaGetSymbolAddress((void**)&q,   g_q);
    cudaGetSymbolAddress((void**)&k,   g_k);
    cudaGetSymbolAddress((void**)&v,   g_v);
    cudaGetSymbolAddress((void**)&xh,  g_xh);
    cudaGetSymbolAddress((void**)&xl,  g_xl);
    cudaGetSymbolAddress((void**)&aoh, g_aoh);
    cudaGetSymbolAddress((void**)&aol, g_aol);
    cudaGetSymbolAddress((void**)&wqh, g_wqh);
    cudaGetSymbolAddress((void**)&wkh, g_wkh);
    cudaGetSymbolAddress((void**)&wvh, g_wvh);
    cudaGetSymbolAddress((void**)&woh, g_woh);
    cudaGetSymbolAddress((void**)&qph, g_qph);
    cudaGetSymbolAddress((void**)&kph, g_kph);
    cudaGetSymbolAddress((void**)&vth, g_vth);

    const int M = BATCH * T_SEQ;   // 8192

    // fused preprocessing (invf + all operand splits)
    prep_all<<<PREP_BLOCKS, 256>>>(x, Wq, Wk, Wv, Wo, xh, xl, wqh, wkh, wvh, woh);

    cudaFuncSetAttribute(gemm_f16_2t, cudaFuncAttributeMaxDynamicSharedMemorySize, GEMM_SMEM);

    // fused Q+K+V projection
    gemm_f16_2t<<<dim3(12, M / 128), 256, GEMM_SMEM>>>(
        M, CDIM, 8, 10, xh, xl,
        wqh, q, CDIM,
        wkh, k, HD,
        wvh, v, HD);

    // fused rmsnorm+rope for q and k -> single fp16
    rmsnorm_rope_fused<<<(M * NH + M) / 8, 256>>>(q, k, qg, kg, qph, kph);

    cudaFuncSetAttribute(transpose_v_f16, cudaFuncAttributeMaxDynamicSharedMemorySize, VT_SMEM);
    transpose_v_f16<<<dim3(T_SEQ / 64, BATCH), 256, VT_SMEM>>>(v, vth);

    cudaFuncSetAttribute(attn_swa_mma, cudaFuncAttributeMaxDynamicSharedMemorySize, ATTN_SMEM);
    attn_swa_mma<<<BATCH * NH * (T_SEQ / 64), 256, ATTN_SMEM>>>(
        qph, kph, vth, aoh, aol);

    // output projection
    gemm_f16_2t<<<dim3(8, M / 128), 256, GEMM_SMEM>>>(
        M, CDIM, 8, 8, aoh, aol,
        woh, out, CDIM,
        woh, out, CDIM,
        woh, out, CDIM);
}

// round 15
// speedup vs baseline: 4.1028x; 1.2635x over previous
#include <cuda_runtime.h>
#include <math.h>
#include <stdint.h>

#define T_SEQ 4096
#define BATCH 2
#define CDIM  1024
#define HD    256
#define NH    4
#define WIN   512

// ---------------- scratch (static device globals; no allocation) ----------------
__device__ float    g_q [(size_t)BATCH * T_SEQ * CDIM];
__device__ float    g_k [(size_t)BATCH * T_SEQ * HD];
__device__ float    g_v [(size_t)BATCH * T_SEQ * HD];
__device__ float    g_invf[HD / 2];
// packed f16x2 operand buffers
__device__ uint32_t g_xh [(size_t)BATCH * T_SEQ * CDIM / 2];
__device__ uint32_t g_aoh[(size_t)BATCH * T_SEQ * CDIM / 2];
__device__ uint32_t g_aol[(size_t)BATCH * T_SEQ * CDIM / 2];
__device__ uint32_t g_wqh[CDIM * CDIM / 2];
__device__ uint32_t g_wkh[HD * CDIM / 2];
__device__ uint32_t g_wvh[HD * CDIM / 2];
__device__ uint32_t g_woh[CDIM * CDIM / 2];
// attention operands (single fp16)
__device__ uint32_t g_qph[(size_t)BATCH * T_SEQ * CDIM / 2];
__device__ uint32_t g_kph[(size_t)BATCH * T_SEQ * HD / 2];
__device__ uint32_t g_vth[(size_t)BATCH * HD * T_SEQ / 2];

// ---------------- common helpers ----------------
__device__ __forceinline__ void split_f16(float x, uint16_t& h, uint16_t& l) {
    asm("cvt.rn.f16.f32 %0, %1;" : "=h"(h) : "f"(x));
    float hf;
    asm("cvt.f32.f16 %0, %1;" : "=f"(hf) : "h"(h));
    float r = x - hf;                       // exact
    asm("cvt.rn.f16.f32 %0, %1;" : "=h"(l) : "f"(r));
}
__device__ __forceinline__ uint16_t to_f16(float x) {
    uint16_t h;
    asm("cvt.rn.f16.f32 %0, %1;" : "=h"(h) : "f"(x));
    return h;
}
__device__ __forceinline__ uint32_t pack2(uint16_t a, uint16_t b) {
    return (uint32_t)a | ((uint32_t)b << 16);
}
__device__ __forceinline__ uint32_t smem_u32p(const void* p) {
    uint32_t a;
    asm("{ .reg .u64 t; cvta.to.shared.u64 t, %1; cvt.u32.u64 %0, t; }" : "=r"(a) : "l"(p));
    return a;
}

#define MMA_F16(d, a, b) \
    asm volatile("mma.sync.aligned.m16n8k16.row.col.f32.f16.f16.f32 " \
        "{%0,%1,%2,%3}, {%4,%5,%6,%7}, {%8,%9}, {%0,%1,%2,%3};" \
        : "+f"((d)[0]), "+f"((d)[1]), "+f"((d)[2]), "+f"((d)[3]) \
        : "r"((a)[0]), "r"((a)[1]), "r"((a)[2]), "r"((a)[3]), \
          "r"((b)[0]), "r"((b)[1]))

#define LDSM4(r0, r1, r2, r3, a) \
    asm volatile("ldmatrix.sync.aligned.m8n8.x4.shared.b16 {%0,%1,%2,%3}, [%4];" \
        : "=r"(r0), "=r"(r1), "=r"(r2), "=r"(r3) : "r"(a))

__device__ __forceinline__ void cpa16(uint32_t sa, const void* ga) {
    asm volatile("cp.async.cg.shared.global [%0], [%1], 16;" :: "r"(sa), "l"(ga));
}
#define CP_COMMIT() asm volatile("cp.async.commit_group;" ::: "memory")
#define CP_WAIT0()  asm volatile("cp.async.wait_group 0;" ::: "memory")

// ============ fused preprocessing: invf + hi-only f16 packs ============
// blocks: [0,4096) x | [4096,4608) Wq | [4608,4736) Wk | [4736,4864) Wv | [4864,5376) Wo
#define PREP_BLOCKS 5376
__global__ __launch_bounds__(256) void prep_all(
    const float* __restrict__ x,  const float* __restrict__ Wq,
    const float* __restrict__ Wk, const float* __restrict__ Wv,
    const float* __restrict__ Wo,
    uint32_t* __restrict__ xh, uint32_t* __restrict__ wqh,
    uint32_t* __restrict__ wkh, uint32_t* __restrict__ wvh,
    uint32_t* __restrict__ woh)
{
    const int bid = blockIdx.x;
    const int tid = threadIdx.x;
    if (bid == 0 && tid < 128) {
        float e = (float)(2 * tid) * (1.0f / HD);
        g_invf[tid] = (float)pow(1000000.0, -(double)e);
    }
    const float* in; uint32_t* oh; int i;
    if (bid < 4096)      { in = x;  oh = xh;  i = bid * 256 + tid; }
    else if (bid < 4608) { in = Wq; oh = wqh; i = (bid - 4096) * 256 + tid; }
    else if (bid < 4736) { in = Wk; oh = wkh; i = (bid - 4608) * 256 + tid; }
    else if (bid < 4864) { in = Wv; oh = wvh; i = (bid - 4736) * 256 + tid; }
    else                 { in = Wo; oh = woh; i = (bid - 4864) * 256 + tid; }

    float4 a = ((const float4*)in)[2 * i];
    float4 b = ((const float4*)in)[2 * i + 1];
    ((uint4*)oh)[i] = make_uint4(
        pack2(to_f16(a.x), to_f16(a.y)), pack2(to_f16(a.z), to_f16(a.w)),
        pack2(to_f16(b.x), to_f16(b.y)), pack2(to_f16(b.z), to_f16(b.w)));
}

// ===== fp16 GEMM, templated on A term-count: C = (Ah[+Al])·Bh^T =====
#define STRP 20
#define PART_U32 (128 * STRP)               // 2560
#define BUF_U32  (3 * PART_U32)             // Ah, Al(optional), Bh
#define GEMM_SMEM (2 * BUF_U32 * 4)         // 61440 B

template<bool TWO>
__global__ __launch_bounds__(256, 2) void gemm_f16(
    int M, int K, int tiles0, int tiles01,
    const uint32_t* __restrict__ Ah, const uint32_t* __restrict__ Al,
    const uint32_t* __restrict__ Bh0, float* __restrict__ C0, int N0,
    const uint32_t* __restrict__ Bh1, float* __restrict__ C1, int N1,
    const uint32_t* __restrict__ Bh2, float* __restrict__ C2, int N2)
{
    extern __shared__ uint32_t s32[];
    const uint32_t sb = smem_u32p(s32);

    const int nt = blockIdx.x;
    const uint32_t* Bh; float* C; int N, ntl;
    if (nt < tiles0)       { Bh = Bh0; C = C0; N = N0; ntl = nt; }
    else if (nt < tiles01) { Bh = Bh1; C = C1; N = N1; ntl = nt - tiles0; }
    else                   { Bh = Bh2; C = C2; N = N2; ntl = nt - tiles01; }

    const int tid    = threadIdx.x;
    const int wid    = tid >> 5;
    const int lane   = tid & 31;
    const int quad   = lane >> 2;
    const int tq     = lane & 3;
    const int warp_m = wid & 3;
    const int warp_n = wid >> 2;
    const int m0 = blockIdx.y << 7;
    const int n0 = ntl << 7;
    const int K2 = K >> 1;

    const int jm   = lane >> 3, jr = lane & 7;
    const int a_ro = (jm & 1) * 8 + jr;
    const int a_ko = (jm >> 1) * 4;
    const int b_go = jm >> 1;
    const int b_ko = (jm & 1) * 4;

    const uint32_t* pAh = Ah + (size_t)m0 * K2;
    const uint32_t* pAl = TWO ? Al + (size_t)m0 * K2 : 0;
    const uint32_t* pBh = Bh + (size_t)n0 * K2;

    const int r0_ = tid >> 2;
    const int r1_ = 64 + r0_;
    const int qd  = (tid & 3) * 4;

#define LOADP(it, buf) do { \
    int kp = (it) * 16; \
    uint32_t sbase = sb + (uint32_t)(buf) * BUF_U32 * 4u; \
    cpa16(sbase + (uint32_t)(0*PART_U32 + r0_*STRP + qd)*4u, pAh + (size_t)r0_*K2 + kp + qd); \
    cpa16(sbase + (uint32_t)(0*PART_U32 + r1_*STRP + qd)*4u, pAh + (size_t)r1_*K2 + kp + qd); \
    if (TWO) { \
        cpa16(sbase + (uint32_t)(1*PART_U32 + r0_*STRP + qd)*4u, pAl + (size_t)r0_*K2 + kp + qd); \
        cpa16(sbase + (uint32_t)(1*PART_U32 + r1_*STRP + qd)*4u, pAl + (size_t)r1_*K2 + kp + qd); \
    } \
    cpa16(sbase + (uint32_t)(2*PART_U32 + r0_*STRP + qd)*4u, pBh + (size_t)r0_*K2 + kp + qd); \
    cpa16(sbase + (uint32_t)(2*PART_U32 + r1_*STRP + qd)*4u, pBh + (size_t)r1_*K2 + kp + qd); \
    CP_COMMIT(); \
} while (0)

    float acc[2][8][4];
#pragma unroll
    for (int mf = 0; mf < 2; mf++)
#pragma unroll
        for (int nf = 0; nf < 8; nf++)
#pragma unroll
            for (int r = 0; r < 4; r++) acc[mf][nf][r] = 0.f;

    const int NT = K / 32;

    LOADP(0, 0);

    for (int it = 0; it < NT; ++it) {
        CP_WAIT0();
        __syncthreads();
        if (it + 1 < NT) LOADP(it + 1, (it + 1) & 1);

        const uint32_t sA = sb + (uint32_t)(it & 1) * BUF_U32 * 4u;
        const uint32_t sB = sA + 2u * PART_U32 * 4u;

#pragma unroll
        for (int ks = 0; ks < 2; ks++) {
            const int kb = ks * 8;
            uint32_t ah[2][4], al[2][4];
#pragma unroll
            for (int mf = 0; mf < 2; mf++) {
                uint32_t ar = sA + (uint32_t)((warp_m*32 + mf*16 + a_ro) * STRP + kb + a_ko) * 4u;
                LDSM4(ah[mf][0], ah[mf][1], ah[mf][2], ah[mf][3], ar);
                if (TWO) LDSM4(al[mf][0], al[mf][1], al[mf][2], al[mf][3], ar + PART_U32*4u);
            }
#pragma unroll
            for (int g = 0; g < 4; g++) {
                uint32_t br = sB + (uint32_t)((warp_n*64 + (2*g + b_go)*8 + jr) * STRP + kb + b_ko) * 4u;
                uint32_t b0h[2], b1h[2];
                LDSM4(b0h[0], b0h[1], b1h[0], b1h[1], br);
#pragma unroll
                for (int mf = 0; mf < 2; mf++) {
                    MMA_F16(acc[mf][2*g],   ah[mf], b0h);
                    if (TWO) MMA_F16(acc[mf][2*g], al[mf], b0h);
                    MMA_F16(acc[mf][2*g+1], ah[mf], b1h);
                    if (TWO) MMA_F16(acc[mf][2*g+1], al[mf], b1h);
                }
            }
        }
    }

#pragma unroll
    for (int mf = 0; mf < 2; mf++) {
        int row = m0 + warp_m * 32 + mf * 16 + quad;
#pragma unroll
        for (int nf = 0; nf < 8; nf++) {
            int col = n0 + warp_n * 64 + nf * 8 + tq * 2;
            *(float2*)(C + (size_t)row * N + col)       = make_float2(acc[mf][nf][0], acc[mf][nf][1]);
            *(float2*)(C + (size_t)(row + 8) * N + col) = make_float2(acc[mf][nf][2], acc[mf][nf][3]);
        }
    }
#undef LOADP
}

// ---------------- fused RMSNorm + RoPE (q + k) -> packed fp16 ----------------
__global__ void rmsnorm_rope_fused(const float* __restrict__ qin, const float* __restrict__ kin,
                                   const float* __restrict__ qg, const float* __restrict__ kg,
                                   uint32_t* __restrict__ qo, uint32_t* __restrict__ ko)
{
    const int NQ = BATCH * T_SEQ * NH;
    int gw   = (int)((blockIdx.x * blockDim.x + threadIdx.x) >> 5);
    int lane = threadIdx.x & 31;

    const float* in; const float* gamma; uint32_t* outp; int t;
    if (gw < NQ) {
        in = qin + (size_t)gw * HD; gamma = qg; outp = qo + (size_t)gw * (HD / 2);
        t = (gw >> 2) & (T_SEQ - 1);
    } else {
        int r = gw - NQ;
        in = kin + (size_t)r * HD; gamma = kg; outp = ko + (size_t)r * (HD / 2);
        t = r & (T_SEQ - 1);
    }

    float v[8];
    *(float4*)&v[0] = *(const float4*)(in + lane * 8);
    *(float4*)&v[4] = *(const float4*)(in + lane * 8 + 4);

    float ss = 0.f;
#pragma unroll
    for (int i = 0; i < 8; i++) ss += v[i] * v[i];
#pragma unroll
    for (int o = 16; o > 0; o >>= 1) ss += __shfl_xor_sync(0xffffffffu, ss, o);

    float r = rsqrtf(ss * (1.0f / HD) + 1e-6f);

    float g[8];
    *(float4*)&g[0] = *(const float4*)(gamma + lane * 8);
    *(float4*)&g[4] = *(const float4*)(gamma + lane * 8 + 4);

    float invf[4];
    *(float4*)invf = *(const float4*)(g_invf + lane * 4);

    float tf = (float)t;
#pragma unroll
    for (int p = 0; p < 4; p++) {
        float ang = tf * invf[p];
        float c, s;
        sincosf(ang, &s, &c);
        float x0 = v[2 * p]     * r * g[2 * p];
        float x1 = v[2 * p + 1] * r * g[2 * p + 1];
        v[2 * p]     = x0 * c - x1 * s;
        v[2 * p + 1] = x0 * s + x1 * c;
    }

    *(uint4*)(outp + lane * 4) = make_uint4(
        pack2(to_f16(v[0]), to_f16(v[1])), pack2(to_f16(v[2]), to_f16(v[3])),
        pack2(to_f16(v[4]), to_f16(v[5])), pack2(to_f16(v[6]), to_f16(v[7])));
}

// ---------------- V transpose -> fp16: v[b][t][d] -> Vt[b][d][t-pairs] ----------
#define VT_SMEM (256 * 69 * 4)
__global__ __launch_bounds__(256) void transpose_v_f16(
    const float* __restrict__ v, uint32_t* __restrict__ vth)
{
    extern __shared__ float st[];
    int b = blockIdx.y, t0 = blockIdx.x * 64;
    int tid = threadIdx.x;
    const float* vb = v + ((size_t)(b * T_SEQ + t0)) * HD;
#pragma unroll
    for (int i = 0; i < 16; i++) {
        int f = i * 256 + tid;
        int t = f >> 6, d4 = (f & 63) * 4;
        float4 x = *(const float4*)(vb + (size_t)t * HD + d4);
        st[(d4 + 0) * 69 + t] = x.x;
        st[(d4 + 1) * 69 + t] = x.y;
        st[(d4 + 2) * 69 + t] = x.z;
        st[(d4 + 3) * 69 + t] = x.w;
    }
    __syncthreads();
    int w = tid >> 5, l = tid & 31;
#pragma unroll
    for (int pass = 0; pass < 32; pass++) {
        int d = pass * 8 + w;
        float x0 = st[d * 69 + 2 * l];
        float x1 = st[d * 69 + 2 * l + 1];
        size_t o = ((size_t)(b * HD + d)) * (T_SEQ / 2) + (t0 >> 1) + l;
        vth[o] = pack2(to_f16(x0), to_f16(x1));
    }
}

// ==== sliding-window flash attention: fp16 Q,K,V,P all single; occupancy 2 ====
#define AQ_STR 132
#define AV_STR 36
#define OFF_Q    0
#define OFF_KV   (64 * AQ_STR)              // K [64][132] or V^T [256][36]
#define OFF_PH   (OFF_KV + 9216)
#define OFF_RED  (OFF_PH + 64 * AV_STR)
#define OFF_RED2 (OFF_RED + 256)
#define OFF_MS   (OFF_RED2 + 256)
#define OFF_LS   (OFF_MS + 64)
#define ATTN_U32 (OFF_LS + 64)
#define ATTN_SMEM (ATTN_U32 * 4)            // ~82 KB -> 2 CTAs/SM

__global__ __launch_bounds__(256, 2) void attn_swa_mma(
    const uint32_t* __restrict__ Qph,
    const uint32_t* __restrict__ Kph,
    const uint32_t* __restrict__ Vth,
    uint32_t* __restrict__ Oh, uint32_t* __restrict__ Ol)
{
    extern __shared__ uint32_t s[];
    const uint32_t sb = smem_u32p(s);
    uint32_t* Ph   = s + OFF_PH;
    float* red     = (float*)(s + OFF_RED);
    float* red2    = (float*)(s + OFF_RED2);
    float* m_s     = (float*)(s + OFF_MS);
    float* l_s     = (float*)(s + OFF_LS);

    const int tid  = threadIdx.x;
    const int wid  = tid >> 5, lane = tid & 31, quad = lane >> 2, tq = lane & 3;
    const int wm   = wid & 1, wn = wid >> 1;
    const int jm   = lane >> 3, jr = lane & 7;
    const int a_ro = (jm & 1) * 8 + jr;
    const int a_ko = (jm >> 1) * 4;
    const int b_go = jm >> 1;
    const int b_ko = (jm & 1) * 4;
    const int qt   = blockIdx.x & 63;
    const int h    = (blockIdx.x >> 6) & 3;
    const int b    = blockIdx.x >> 8;
    const int q0   = qt << 6;

    const uint32_t* qh_g = Qph + ((size_t)(b * T_SEQ + q0)) * (CDIM / 2) + h * (HD / 2);
    const uint32_t* kh_g = Kph + (size_t)b * T_SEQ * (HD / 2);
    const uint32_t* vh_g = Vth + (size_t)b * HD * (T_SEQ / 2);

    // ---- Q tile ----
#pragma unroll
    for (int i = 0; i < 8; i++) {
        int f = i * 256 + tid, row = f >> 5, c4 = (f & 31) * 4;
        cpa16(sb + (uint32_t)(OFF_Q + row * AQ_STR + c4) * 4u, qh_g + (size_t)row * (CDIM / 2) + c4);
    }
    CP_COMMIT();
    if (tid < 64) { m_s[tid] = -1e30f; l_s[tid] = 0.f; }
    CP_WAIT0();
    __syncthreads();

    float oacc[2][8][4];
#pragma unroll
    for (int mf = 0; mf < 2; mf++)
#pragma unroll
        for (int nf = 0; nf < 8; nf++)
#pragma unroll
            for (int r = 0; r < 4; r++) oacc[mf][nf][r] = 0.f;

    int kt0 = q0 - WIN; if (kt0 < 0) kt0 = 0;

    for (int kt = kt0; kt <= q0; kt += 64) {
        __syncthreads();   // A

        // ---- K tile ----
#pragma unroll
        for (int i = 0; i < 8; i++) {
            int f = i * 256 + tid, row = f >> 5, c4 = (f & 31) * 4;
            cpa16(sb + (uint32_t)(OFF_KV + row * AQ_STR + c4) * 4u, kh_g + (size_t)(kt + row) * (HD / 2) + c4);
        }
        CP_COMMIT();
        CP_WAIT0();
        __syncthreads();   // B

        // ---- S = Qh Kh^T ----
        float sacc[2][2][4];
#pragma unroll
        for (int mf = 0; mf < 2; mf++)
#pragma unroll
            for (int nf = 0; nf < 2; nf++)
#pragma unroll
                for (int r = 0; r < 4; r++) sacc[mf][nf][r] = 0.f;

#pragma unroll
        for (int ks = 0; ks < 16; ks++) {
            const int kb = ks * 8;
            uint32_t ah[2][4];
#pragma unroll
            for (int mf = 0; mf < 2; mf++) {
                uint32_t ar = sb + (uint32_t)(OFF_Q + (wm*32 + mf*16 + a_ro) * AQ_STR + kb + a_ko) * 4u;
                LDSM4(ah[mf][0], ah[mf][1], ah[mf][2], ah[mf][3], ar);
            }
            uint32_t br = sb + (uint32_t)(OFF_KV + (wn*16 + b_go*8 + jr) * AQ_STR + kb + b_ko) * 4u;
            uint32_t b0h[2], b1h[2];
            LDSM4(b0h[0], b0h[1], b1h[0], b1h[1], br);
#pragma unroll
            for (int mf = 0; mf < 2; mf++) {
                MMA_F16(sacc[mf][0], ah[mf], b0h);
                MMA_F16(sacc[mf][1], ah[mf], b1h);
            }
        }

        // ---- mask + scale + row max ----
#pragma unroll
        for (int mf = 0; mf < 2; mf++)
#pragma unroll
            for (int half = 0; half < 2; half++) {
                int rowl = wm * 32 + mf * 16 + quad + half * 8;
                int irow = q0 + rowl;
                float mt = -1e30f;
#pragma unroll
                for (int nf = 0; nf < 2; nf++)
#pragma unroll
                    for (int p = 0; p < 2; p++) {
                        int j = kt + wn * 16 + nf * 8 + tq * 2 + p;
                        bool ok = (j <= irow) && (j >= irow - WIN);
                        float x = ok ? sacc[mf][nf][half * 2 + p] * 0.0625f : -1e30f;
                        sacc[mf][nf][half * 2 + p] = x;
                        mt = fmaxf(mt, x);
                    }
                mt = fmaxf(mt, __shfl_xor_sync(0xffffffffu, mt, 1));
                mt = fmaxf(mt, __shfl_xor_sync(0xffffffffu, mt, 2));
                if (tq == 0) red[wn * 64 + rowl] = mt;
            }
        __syncthreads();   // C

        // ---- V^T tile (overlaps softmax) ----
#pragma unroll
        for (int i = 0; i < 8; i++) {
            int f = i * 256 + tid, d = f >> 3, c4 = (f & 7) * 4;
            cpa16(sb + (uint32_t)(OFF_KV + d * AV_STR + c4) * 4u, vh_g + (size_t)d * (T_SEQ / 2) + (kt >> 1) + c4);
        }
        CP_COMMIT();

        float mn_loc[2][2], corr_loc[2][2];
#pragma unroll
        for (int mf = 0; mf < 2; mf++)
#pragma unroll
            for (int half = 0; half < 2; half++) {
                int rowl = wm * 32 + mf * 16 + quad + half * 8;
                float mt = fmaxf(fmaxf(red[rowl], red[64 + rowl]),
                                 fmaxf(red[128 + rowl], red[192 + rowl]));
                float mo = m_s[rowl];
                float mn = fmaxf(mo, mt);
                mn_loc[mf][half]   = mn;
                corr_loc[mf][half] = __expf(mo - mn);
            }

        // ---- P = exp(S - m) -> single fp16; row sums ----
#pragma unroll
        for (int mf = 0; mf < 2; mf++)
#pragma unroll
            for (int half = 0; half < 2; half++) {
                int rowl = wm * 32 + mf * 16 + quad + half * 8;
                float mn = mn_loc[mf][half];
                float rs = 0.f;
#pragma unroll
                for (int nf = 0; nf < 2; nf++) {
                    float p0 = __expf(sacc[mf][nf][half * 2 + 0] - mn);
                    float p1 = __expf(sacc[mf][nf][half * 2 + 1] - mn);
                    rs += p0 + p1;
                    Ph[rowl * AV_STR + wn * 8 + nf * 4 + tq] = pack2(to_f16(p0), to_f16(p1));
                }
                rs += __shfl_xor_sync(0xffffffffu, rs, 1);
                rs += __shfl_xor_sync(0xffffffffu, rs, 2);
                if (tq == 0) red2[wn * 64 + rowl] = rs;
            }
        __syncthreads();   // E

        if (wid < 2 && tq == 0) {
#pragma unroll
            for (int mf = 0; mf < 2; mf++)
#pragma unroll
                for (int half = 0; half < 2; half++) {
                    int rowl = wid * 32 + mf * 16 + quad + half * 8;
                    l_s[rowl] = l_s[rowl] * corr_loc[mf][half] +
                                red2[rowl] + red2[64 + rowl] + red2[128 + rowl] + red2[192 + rowl];
                    m_s[rowl] = mn_loc[mf][half];
                }
        }
#pragma unroll
        for (int mf = 0; mf < 2; mf++) {
            float c0 = corr_loc[mf][0], c1 = corr_loc[mf][1];
#pragma unroll
            for (int nf = 0; nf < 8; nf++) {
                oacc[mf][nf][0] *= c0; oacc[mf][nf][1] *= c0;
                oacc[mf][nf][2] *= c1; oacc[mf][nf][3] *= c1;
            }
        }
        CP_WAIT0();
        __syncthreads();   // F

        // ---- O += Ph Vh ----
#pragma unroll
        for (int kk = 0; kk < 4; kk++) {
            const int kb = kk * 8;
            uint32_t pah[2][4];
#pragma unroll
            for (int mf = 0; mf < 2; mf++) {
                uint32_t ar = sb + (uint32_t)(OFF_PH + (wm*32 + mf*16 + a_ro) * AV_STR + kb + a_ko) * 4u;
                LDSM4(pah[mf][0], pah[mf][1], pah[mf][2], pah[mf][3], ar);
            }
#pragma unroll
            for (int g = 0; g < 4; g++) {
                uint32_t br = sb + (uint32_t)(OFF_KV + (wn*64 + (2*g + b_go)*8 + jr) * AV_STR + kb + b_ko) * 4u;
                uint32_t v0h[2], v1h[2];
                LDSM4(v0h[0], v0h[1], v1h[0], v1h[1], br);
#pragma unroll
                for (int mf = 0; mf < 2; mf++) {
                    MMA_F16(oacc[mf][2*g],   pah[mf], v0h);
                    MMA_F16(oacc[mf][2*g+1], pah[mf], v1h);
                }
            }
        }
    }

    // ---- epilogue: write ao as packed f16x2 hi/lo (Wo GEMM operand, 2-term) ----
#pragma unroll
    for (int mf = 0; mf < 2; mf++) {
        int r0 = wm * 32 + mf * 16 + quad;
        float i0 = 1.f / l_s[r0], i1 = 1.f / l_s[r0 + 8];
        size_t base0 = ((size_t)(b * T_SEQ + q0 + r0)) * (CDIM / 2) + h * (HD / 2);
        size_t base1 = base0 + 8 * (CDIM / 2);
#pragma unroll
        for (int nf = 0; nf < 8; nf++) {
            int cp_ = wn * 32 + nf * 4 + tq;
            uint16_t h0, l0, h1, l1;
            split_f16(oacc[mf][nf][0] * i0, h0, l0);
            split_f16(oacc[mf][nf][1] * i0, h1, l1);
            Oh[base0 + cp_] = pack2(h0, h1);
            Ol[base0 + cp_] = pack2(l0, l1);
            split_f16(oacc[mf][nf][2] * i1, h0, l0);
            split_f16(oacc[mf][nf][3] * i1, h1, l1);
            Oh[base1 + cp_] = pack2(h0, h1);
            Ol[base1 + cp_] = pack2(l0, l1);
        }
    }
}

// ---------------- launch ----------------
extern "C" void kernel_launch(void* const* d_in, const int* in_sizes, int n_in,
                              void* d_out, int out_size)
{
    const float* x  = (const float*)d_in[0];
    const float* Wq = (const float*)d_in[1];
    const float* Wk = (const float*)d_in[2];
    const float* Wv = (const float*)d_in[3];
    const float* Wo = (const float*)d_in[4];
    const float* qg = (const float*)d_in[5];
    const float* kg = (const float*)d_in[6];
    float* out = (float*)d_out;

    float *q, *k, *v;
    uint32_t *xh, *aoh, *aol, *wqh, *wkh, *wvh, *woh;
    uint32_t *qph, *kph, *vth;
    cudaGetSymbolAddress((void**)&q,   g_q);
    cudaGetSymbolAddress((void**)&k,   g_k);
    cudaGetSymbolAddress((void**)&v,   g_v);
    cudaGetSymbolAddress((void**)&xh,  g_xh);
    cudaGetSymbolAddress((void**)&aoh, g_aoh);
    cudaGetSymbolAddress((void**)&aol, g_aol);
    cudaGetSymbolAddress((void**)&wqh, g_wqh);
    cudaGetSymbolAddress((void**)&wkh, g_wkh);
    cudaGetSymbolAddress((void**)&wvh, g_wvh);
    cudaGetSymbolAddress((void**)&woh, g_woh);
    cudaGetSymbolAddress((void**)&qph, g_qph);
    cudaGetSymbolAddress((void**)&kph, g_kph);
    cudaGetSymbolAddress((void**)&vth, g_vth);

    const int M = BATCH * T_SEQ;   // 8192

    prep_all<<<PREP_BLOCKS, 256>>>(x, Wq, Wk, Wv, Wo, xh, wqh, wkh, wvh, woh);

    cudaFuncSetAttribute(gemm_f16<false>, cudaFuncAttributeMaxDynamicSharedMemorySize, GEMM_SMEM);
    cudaFuncSetAttribute(gemm_f16<true>,  cudaFuncAttributeMaxDynamicSharedMemorySize, GEMM_SMEM);

    // fused Q+K+V projection (single-term A)
    gemm_f16<false><<<dim3(12, M / 128), 256, GEMM_SMEM>>>(
        M, CDIM, 8, 10, xh, xh,
        wqh, q, CDIM,
        wkh, k, HD,
        wvh, v, HD);

    rmsnorm_rope_fused<<<(M * NH + M) / 8, 256>>>(q, k, qg, kg, qph, kph);

    cudaFuncSetAttribute(transpose_v_f16, cudaFuncAttributeMaxDynamicSharedMemorySize, VT_SMEM);
    transpose_v_f16<<<dim3(T_SEQ / 64, BATCH), 256, VT_SMEM>>>(v, vth);

    cudaFuncSetAttribute(attn_swa_mma, cudaFuncAttributeMaxDynamicSharedMemorySize, ATTN_SMEM);
    attn_swa_mma<<<BATCH * NH * (T_SEQ / 64), 256, ATTN_SMEM>>>(
        qph, kph, vth, aoh, aol);

    // output projection (2-term A: ao hi/lo)
    gemm_f16<true><<<dim3(8, M / 128), 256, GEMM_SMEM>>>(
        M, CDIM, 8, 8, aoh, aol,
        woh, out, CDIM,
        woh, out, CDIM,
        woh, out, CDIM);
}

// round 16
// speedup vs baseline: 4.7741x; 1.1636x over previous
#include <cuda_runtime.h>
#include <math.h>
#include <stdint.h>

#define T_SEQ 4096
#define BATCH 2
#define CDIM  1024
#define HD    256
#define NH    4
#define WIN   512

// ---------------- scratch (static device globals; no allocation) ----------------
__device__ float    g_q [(size_t)BATCH * T_SEQ * CDIM];
__device__ float    g_k [(size_t)BATCH * T_SEQ * HD];
__device__ float    g_v [(size_t)BATCH * T_SEQ * HD];
__device__ float    g_invf[HD / 2];
// packed f16x2 operand buffers
__device__ uint32_t g_xh [(size_t)BATCH * T_SEQ * CDIM / 2];
__device__ uint32_t g_aoh[(size_t)BATCH * T_SEQ * CDIM / 2];
__device__ uint32_t g_wqh[CDIM * CDIM / 2];
__device__ uint32_t g_wkh[HD * CDIM / 2];
__device__ uint32_t g_wvh[HD * CDIM / 2];
__device__ uint32_t g_woh[CDIM * CDIM / 2];
// attention operands (single fp16)
__device__ uint32_t g_qph[(size_t)BATCH * T_SEQ * CDIM / 2];
__device__ uint32_t g_kph[(size_t)BATCH * T_SEQ * HD / 2];
__device__ uint32_t g_vth[(size_t)BATCH * HD * T_SEQ / 2];

// ---------------- common helpers ----------------
__device__ __forceinline__ uint16_t to_f16(float x) {
    uint16_t h;
    asm("cvt.rn.f16.f32 %0, %1;" : "=h"(h) : "f"(x));
    return h;
}
__device__ __forceinline__ uint32_t pack2(uint16_t a, uint16_t b) {
    return (uint32_t)a | ((uint32_t)b << 16);
}
__device__ __forceinline__ uint32_t smem_u32p(const void* p) {
    uint32_t a;
    asm("{ .reg .u64 t; cvta.to.shared.u64 t, %1; cvt.u32.u64 %0, t; }" : "=r"(a) : "l"(p));
    return a;
}

#define MMA_F16(d, a, b) \
    asm volatile("mma.sync.aligned.m16n8k16.row.col.f32.f16.f16.f32 " \
        "{%0,%1,%2,%3}, {%4,%5,%6,%7}, {%8,%9}, {%0,%1,%2,%3};" \
        : "+f"((d)[0]), "+f"((d)[1]), "+f"((d)[2]), "+f"((d)[3]) \
        : "r"((a)[0]), "r"((a)[1]), "r"((a)[2]), "r"((a)[3]), \
          "r"((b)[0]), "r"((b)[1]))

#define LDSM4(r0, r1, r2, r3, a) \
    asm volatile("ldmatrix.sync.aligned.m8n8.x4.shared.b16 {%0,%1,%2,%3}, [%4];" \
        : "=r"(r0), "=r"(r1), "=r"(r2), "=r"(r3) : "r"(a))

__device__ __forceinline__ void cpa16(uint32_t sa, const void* ga) {
    asm volatile("cp.async.cg.shared.global [%0], [%1], 16;" :: "r"(sa), "l"(ga));
}
#define CP_COMMIT() asm volatile("cp.async.commit_group;" ::: "memory")
#define CP_WAIT0()  asm volatile("cp.async.wait_group 0;" ::: "memory")

// ============ fused preprocessing: invf + hi-only f16 packs ============
#define PREP_BLOCKS 5376
__global__ __launch_bounds__(256) void prep_all(
    const float* __restrict__ x,  const float* __restrict__ Wq,
    const float* __restrict__ Wk, const float* __restrict__ Wv,
    const float* __restrict__ Wo,
    uint32_t* __restrict__ xh, uint32_t* __restrict__ wqh,
    uint32_t* __restrict__ wkh, uint32_t* __restrict__ wvh,
    uint32_t* __restrict__ woh)
{
    const int bid = blockIdx.x;
    const int tid = threadIdx.x;
    if (bid == 0 && tid < 128) {
        float e = (float)(2 * tid) * (1.0f / HD);
        g_invf[tid] = (float)pow(1000000.0, -(double)e);
    }
    const float* in; uint32_t* oh; int i;
    if (bid < 4096)      { in = x;  oh = xh;  i = bid * 256 + tid; }
    else if (bid < 4608) { in = Wq; oh = wqh; i = (bid - 4096) * 256 + tid; }
    else if (bid < 4736) { in = Wk; oh = wkh; i = (bid - 4608) * 256 + tid; }
    else if (bid < 4864) { in = Wv; oh = wvh; i = (bid - 4736) * 256 + tid; }
    else                 { in = Wo; oh = woh; i = (bid - 4864) * 256 + tid; }

    float4 a = ((const float4*)in)[2 * i];
    float4 b = ((const float4*)in)[2 * i + 1];
    ((uint4*)oh)[i] = make_uint4(
        pack2(to_f16(a.x), to_f16(a.y)), pack2(to_f16(a.z), to_f16(a.w)),
        pack2(to_f16(b.x), to_f16(b.y)), pack2(to_f16(b.z), to_f16(b.w)));
}

// ===== fp16 GEMM, templated on A term-count: C = (Ah[+Al])·Bh^T =====
#define STRP 20
#define PART_U32 (128 * STRP)
#define BUF_U32  (3 * PART_U32)
#define GEMM_SMEM (2 * BUF_U32 * 4)

template<bool TWO>
__global__ __launch_bounds__(256, 2) void gemm_f16(
    int M, int K, int tiles0, int tiles01,
    const uint32_t* __restrict__ Ah, const uint32_t* __restrict__ Al,
    const uint32_t* __restrict__ Bh0, float* __restrict__ C0, int N0,
    const uint32_t* __restrict__ Bh1, float* __restrict__ C1, int N1,
    const uint32_t* __restrict__ Bh2, float* __restrict__ C2, int N2)
{
    extern __shared__ uint32_t s32[];
    const uint32_t sb = smem_u32p(s32);

    const int nt = blockIdx.x;
    const uint32_t* Bh; float* C; int N, ntl;
    if (nt < tiles0)       { Bh = Bh0; C = C0; N = N0; ntl = nt; }
    else if (nt < tiles01) { Bh = Bh1; C = C1; N = N1; ntl = nt - tiles0; }
    else                   { Bh = Bh2; C = C2; N = N2; ntl = nt - tiles01; }

    const int tid    = threadIdx.x;
    const int wid    = tid >> 5;
    const int lane   = tid & 31;
    const int quad   = lane >> 2;
    const int tq     = lane & 3;
    const int warp_m = wid & 3;
    const int warp_n = wid >> 2;
    const int m0 = blockIdx.y << 7;
    const int n0 = ntl << 7;
    const int K2 = K >> 1;

    const int jm   = lane >> 3, jr = lane & 7;
    const int a_ro = (jm & 1) * 8 + jr;
    const int a_ko = (jm >> 1) * 4;
    const int b_go = jm >> 1;
    const int b_ko = (jm & 1) * 4;

    const uint32_t* pAh = Ah + (size_t)m0 * K2;
    const uint32_t* pAl = TWO ? Al + (size_t)m0 * K2 : 0;
    const uint32_t* pBh = Bh + (size_t)n0 * K2;

    const int r0_ = tid >> 2;
    const int r1_ = 64 + r0_;
    const int qd  = (tid & 3) * 4;

#define LOADP(it, buf) do { \
    int kp = (it) * 16; \
    uint32_t sbase = sb + (uint32_t)(buf) * BUF_U32 * 4u; \
    cpa16(sbase + (uint32_t)(0*PART_U32 + r0_*STRP + qd)*4u, pAh + (size_t)r0_*K2 + kp + qd); \
    cpa16(sbase + (uint32_t)(0*PART_U32 + r1_*STRP + qd)*4u, pAh + (size_t)r1_*K2 + kp + qd); \
    if (TWO) { \
        cpa16(sbase + (uint32_t)(1*PART_U32 + r0_*STRP + qd)*4u, pAl + (size_t)r0_*K2 + kp + qd); \
        cpa16(sbase + (uint32_t)(1*PART_U32 + r1_*STRP + qd)*4u, pAl + (size_t)r1_*K2 + kp + qd); \
    } \
    cpa16(sbase + (uint32_t)(2*PART_U32 + r0_*STRP + qd)*4u, pBh + (size_t)r0_*K2 + kp + qd); \
    cpa16(sbase + (uint32_t)(2*PART_U32 + r1_*STRP + qd)*4u, pBh + (size_t)r1_*K2 + kp + qd); \
    CP_COMMIT(); \
} while (0)

    float acc[2][8][4];
#pragma unroll
    for (int mf = 0; mf < 2; mf++)
#pragma unroll
        for (int nf = 0; nf < 8; nf++)
#pragma unroll
            for (int r = 0; r < 4; r++) acc[mf][nf][r] = 0.f;

    const int NT = K / 32;

    LOADP(0, 0);

    for (int it = 0; it < NT; ++it) {
        CP_WAIT0();
        __syncthreads();
        if (it + 1 < NT) LOADP(it + 1, (it + 1) & 1);

        const uint32_t sA = sb + (uint32_t)(it & 1) * BUF_U32 * 4u;
        const uint32_t sB = sA + 2u * PART_U32 * 4u;

#pragma unroll
        for (int ks = 0; ks < 2; ks++) {
            const int kb = ks * 8;
            uint32_t ah[2][4], al[2][4];
#pragma unroll
            for (int mf = 0; mf < 2; mf++) {
                uint32_t ar = sA + (uint32_t)((warp_m*32 + mf*16 + a_ro) * STRP + kb + a_ko) * 4u;
                LDSM4(ah[mf][0], ah[mf][1], ah[mf][2], ah[mf][3], ar);
                if (TWO) LDSM4(al[mf][0], al[mf][1], al[mf][2], al[mf][3], ar + PART_U32*4u);
            }
#pragma unroll
            for (int g = 0; g < 4; g++) {
                uint32_t br = sB + (uint32_t)((warp_n*64 + (2*g + b_go)*8 + jr) * STRP + kb + b_ko) * 4u;
                uint32_t b0h[2], b1h[2];
                LDSM4(b0h[0], b0h[1], b1h[0], b1h[1], br);
#pragma unroll
                for (int mf = 0; mf < 2; mf++) {
                    MMA_F16(acc[mf][2*g],   ah[mf], b0h);
                    if (TWO) MMA_F16(acc[mf][2*g], al[mf], b0h);
                    MMA_F16(acc[mf][2*g+1], ah[mf], b1h);
                    if (TWO) MMA_F16(acc[mf][2*g+1], al[mf], b1h);
                }
            }
        }
    }

#pragma unroll
    for (int mf = 0; mf < 2; mf++) {
        int row = m0 + warp_m * 32 + mf * 16 + quad;
#pragma unroll
        for (int nf = 0; nf < 8; nf++) {
            int col = n0 + warp_n * 64 + nf * 8 + tq * 2;
            *(float2*)(C + (size_t)row * N + col)       = make_float2(acc[mf][nf][0], acc[mf][nf][1]);
            *(float2*)(C + (size_t)(row + 8) * N + col) = make_float2(acc[mf][nf][2], acc[mf][nf][3]);
        }
    }
#undef LOADP
}

// ---------------- fused RMSNorm + RoPE (q + k) -> packed fp16 ----------------
__global__ void rmsnorm_rope_fused(const float* __restrict__ qin, const float* __restrict__ kin,
                                   const float* __restrict__ qg, const float* __restrict__ kg,
                                   uint32_t* __restrict__ qo, uint32_t* __restrict__ ko)
{
    const int NQ = BATCH * T_SEQ * NH;
    int gw   = (int)((blockIdx.x * blockDim.x + threadIdx.x) >> 5);
    int lane = threadIdx.x & 31;

    const float* in; const float* gamma; uint32_t* outp; int t;
    if (gw < NQ) {
        in = qin + (size_t)gw * HD; gamma = qg; outp = qo + (size_t)gw * (HD / 2);
        t = (gw >> 2) & (T_SEQ - 1);
    } else {
        int r = gw - NQ;
        in = kin + (size_t)r * HD; gamma = kg; outp = ko + (size_t)r * (HD / 2);
        t = r & (T_SEQ - 1);
    }

    float v[8];
    *(float4*)&v[0] = *(const float4*)(in + lane * 8);
    *(float4*)&v[4] = *(const float4*)(in + lane * 8 + 4);

    float ss = 0.f;
#pragma unroll
    for (int i = 0; i < 8; i++) ss += v[i] * v[i];
#pragma unroll
    for (int o = 16; o > 0; o >>= 1) ss += __shfl_xor_sync(0xffffffffu, ss, o);

    float r = rsqrtf(ss * (1.0f / HD) + 1e-6f);

    float g[8];
    *(float4*)&g[0] = *(const float4*)(gamma + lane * 8);
    *(float4*)&g[4] = *(const float4*)(gamma + lane * 8 + 4);

    float invf[4];
    *(float4*)invf = *(const float4*)(g_invf + lane * 4);

    float tf = (float)t;
#pragma unroll
    for (int p = 0; p < 4; p++) {
        float ang = tf * invf[p];
        float c, s;
        sincosf(ang, &s, &c);
        float x0 = v[2 * p]     * r * g[2 * p];
        float x1 = v[2 * p + 1] * r * g[2 * p + 1];
        v[2 * p]     = x0 * c - x1 * s;
        v[2 * p + 1] = x0 * s + x1 * c;
    }

    *(uint4*)(outp + lane * 4) = make_uint4(
        pack2(to_f16(v[0]), to_f16(v[1])), pack2(to_f16(v[2]), to_f16(v[3])),
        pack2(to_f16(v[4]), to_f16(v[5])), pack2(to_f16(v[6]), to_f16(v[7])));
}

// ---------------- V transpose -> fp16: v[b][t][d] -> Vt[b][d][t-pairs] ----------
#define VT_SMEM (256 * 69 * 4)
__global__ __launch_bounds__(256) void transpose_v_f16(
    const float* __restrict__ v, uint32_t* __restrict__ vth)
{
    extern __shared__ float st[];
    int b = blockIdx.y, t0 = blockIdx.x * 64;
    int tid = threadIdx.x;
    const float* vb = v + ((size_t)(b * T_SEQ + t0)) * HD;
#pragma unroll
    for (int i = 0; i < 16; i++) {
        int f = i * 256 + tid;
        int t = f >> 6, d4 = (f & 63) * 4;
        float4 x = *(const float4*)(vb + (size_t)t * HD + d4);
        st[(d4 + 0) * 69 + t] = x.x;
        st[(d4 + 1) * 69 + t] = x.y;
        st[(d4 + 2) * 69 + t] = x.z;
        st[(d4 + 3) * 69 + t] = x.w;
    }
    __syncthreads();
    int w = tid >> 5, l = tid & 31;
#pragma unroll
    for (int pass = 0; pass < 32; pass++) {
        int d = pass * 8 + w;
        float x0 = st[d * 69 + 2 * l];
        float x1 = st[d * 69 + 2 * l + 1];
        size_t o = ((size_t)(b * HD + d)) * (T_SEQ / 2) + (t0 >> 1) + l;
        vth[o] = pack2(to_f16(x0), to_f16(x1));
    }
}

// ==== sliding-window flash attention: fp16 Q,K,V,P single; ao single fp16 out ====
#define AQ_STR 132
#define AV_STR 36
#define OFF_Q    0
#define OFF_KV   (64 * AQ_STR)
#define OFF_PH   (OFF_KV + 9216)
#define OFF_RED  (OFF_PH + 64 * AV_STR)
#define OFF_RED2 (OFF_RED + 256)
#define OFF_MS   (OFF_RED2 + 256)
#define OFF_LS   (OFF_MS + 64)
#define ATTN_U32 (OFF_LS + 64)
#define ATTN_SMEM (ATTN_U32 * 4)            // ~82 KB -> 2 CTAs/SM

__global__ __launch_bounds__(256, 2) void attn_swa_mma(
    const uint32_t* __restrict__ Qph,
    const uint32_t* __restrict__ Kph,
    const uint32_t* __restrict__ Vth,
    uint32_t* __restrict__ Oh)
{
    extern __shared__ uint32_t s[];
    const uint32_t sb = smem_u32p(s);
    uint32_t* Ph   = s + OFF_PH;
    float* red     = (float*)(s + OFF_RED);
    float* red2    = (float*)(s + OFF_RED2);
    float* m_s     = (float*)(s + OFF_MS);
    float* l_s     = (float*)(s + OFF_LS);

    const int tid  = threadIdx.x;
    const int wid  = tid >> 5, lane = tid & 31, quad = lane >> 2, tq = lane & 3;
    const int wm   = wid & 1, wn = wid >> 1;
    const int jm   = lane >> 3, jr = lane & 7;
    const int a_ro = (jm & 1) * 8 + jr;
    const int a_ko = (jm >> 1) * 4;
    const int b_go = jm >> 1;
    const int b_ko = (jm & 1) * 4;
    const int qt   = blockIdx.x & 63;
    const int h    = (blockIdx.x >> 6) & 3;
    const int b    = blockIdx.x >> 8;
    const int q0   = qt << 6;

    const uint32_t* qh_g = Qph + ((size_t)(b * T_SEQ + q0)) * (CDIM / 2) + h * (HD / 2);
    const uint32_t* kh_g = Kph + (size_t)b * T_SEQ * (HD / 2);
    const uint32_t* vh_g = Vth + (size_t)b * HD * (T_SEQ / 2);

    // ---- Q tile ----
#pragma unroll
    for (int i = 0; i < 8; i++) {
        int f = i * 256 + tid, row = f >> 5, c4 = (f & 31) * 4;
        cpa16(sb + (uint32_t)(OFF_Q + row * AQ_STR + c4) * 4u, qh_g + (size_t)row * (CDIM / 2) + c4);
    }
    CP_COMMIT();
    if (tid < 64) { m_s[tid] = -1e30f; l_s[tid] = 0.f; }
    CP_WAIT0();
    __syncthreads();

    float oacc[2][8][4];
#pragma unroll
    for (int mf = 0; mf < 2; mf++)
#pragma unroll
        for (int nf = 0; nf < 8; nf++)
#pragma unroll
            for (int r = 0; r < 4; r++) oacc[mf][nf][r] = 0.f;

    int kt0 = q0 - WIN; if (kt0 < 0) kt0 = 0;

    for (int kt = kt0; kt <= q0; kt += 64) {
        __syncthreads();   // A

        // ---- K tile ----
#pragma unroll
        for (int i = 0; i < 8; i++) {
            int f = i * 256 + tid, row = f >> 5, c4 = (f & 31) * 4;
            cpa16(sb + (uint32_t)(OFF_KV + row * AQ_STR + c4) * 4u, kh_g + (size_t)(kt + row) * (HD / 2) + c4);
        }
        CP_COMMIT();
        CP_WAIT0();
        __syncthreads();   // B

        // ---- S = Qh Kh^T ----
        float sacc[2][2][4];
#pragma unroll
        for (int mf = 0; mf < 2; mf++)
#pragma unroll
            for (int nf = 0; nf < 2; nf++)
#pragma unroll
                for (int r = 0; r < 4; r++) sacc[mf][nf][r] = 0.f;

#pragma unroll
        for (int ks = 0; ks < 16; ks++) {
            const int kb = ks * 8;
            uint32_t ah[2][4];
#pragma unroll
            for (int mf = 0; mf < 2; mf++) {
                uint32_t ar = sb + (uint32_t)(OFF_Q + (wm*32 + mf*16 + a_ro) * AQ_STR + kb + a_ko) * 4u;
                LDSM4(ah[mf][0], ah[mf][1], ah[mf][2], ah[mf][3], ar);
            }
            uint32_t br = sb + (uint32_t)(OFF_KV + (wn*16 + b_go*8 + jr) * AQ_STR + kb + b_ko) * 4u;
            uint32_t b0h[2], b1h[2];
            LDSM4(b0h[0], b0h[1], b1h[0], b1h[1], br);
#pragma unroll
            for (int mf = 0; mf < 2; mf++) {
                MMA_F16(sacc[mf][0], ah[mf], b0h);
                MMA_F16(sacc[mf][1], ah[mf], b1h);
            }
        }

        // ---- mask + scale + row max ----
#pragma unroll
        for (int mf = 0; mf < 2; mf++)
#pragma unroll
            for (int half = 0; half < 2; half++) {
                int rowl = wm * 32 + mf * 16 + quad + half * 8;
                int irow = q0 + rowl;
                float mt = -1e30f;
#pragma unroll
                for (int nf = 0; nf < 2; nf++)
#pragma unroll
                    for (int p = 0; p < 2; p++) {
                        int j = kt + wn * 16 + nf * 8 + tq * 2 + p;
                        bool ok = (j <= irow) && (j >= irow - WIN);
                        float x = ok ? sacc[mf][nf][half * 2 + p] * 0.0625f : -1e30f;
                        sacc[mf][nf][half * 2 + p] = x;
                        mt = fmaxf(mt, x);
                    }
                mt = fmaxf(mt, __shfl_xor_sync(0xffffffffu, mt, 1));
                mt = fmaxf(mt, __shfl_xor_sync(0xffffffffu, mt, 2));
                if (tq == 0) red[wn * 64 + rowl] = mt;
            }
        __syncthreads();   // C

        // ---- V^T tile (overlaps softmax) ----
#pragma unroll
        for (int i = 0; i < 8; i++) {
            int f = i * 256 + tid, d = f >> 3, c4 = (f & 7) * 4;
            cpa16(sb + (uint32_t)(OFF_KV + d * AV_STR + c4) * 4u, vh_g + (size_t)d * (T_SEQ / 2) + (kt >> 1) + c4);
        }
        CP_COMMIT();

        float mn_loc[2][2], corr_loc[2][2];
#pragma unroll
        for (int mf = 0; mf < 2; mf++)
#pragma unroll
            for (int half = 0; half < 2; half++) {
                int rowl = wm * 32 + mf * 16 + quad + half * 8;
                float mt = fmaxf(fmaxf(red[rowl], red[64 + rowl]),
                                 fmaxf(red[128 + rowl], red[192 + rowl]));
                float mo = m_s[rowl];
                float mn = fmaxf(mo, mt);
                mn_loc[mf][half]   = mn;
                corr_loc[mf][half] = __expf(mo - mn);
            }

        // ---- P = exp(S - m) -> single fp16; row sums ----
#pragma unroll
        for (int mf = 0; mf < 2; mf++)
#pragma unroll
            for (int half = 0; half < 2; half++) {
                int rowl = wm * 32 + mf * 16 + quad + half * 8;
                float mn = mn_loc[mf][half];
                float rs = 0.f;
#pragma unroll
                for (int nf = 0; nf < 2; nf++) {
                    float p0 = __expf(sacc[mf][nf][half * 2 + 0] - mn);
                    float p1 = __expf(sacc[mf][nf][half * 2 + 1] - mn);
                    rs += p0 + p1;
                    Ph[rowl * AV_STR + wn * 8 + nf * 4 + tq] = pack2(to_f16(p0), to_f16(p1));
                }
                rs += __shfl_xor_sync(0xffffffffu, rs, 1);
                rs += __shfl_xor_sync(0xffffffffu, rs, 2);
                if (tq == 0) red2[wn * 64 + rowl] = rs;
            }
        __syncthreads();   // E

        if (wid < 2 && tq == 0) {
#pragma unroll
            for (int mf = 0; mf < 2; mf++)
#pragma unroll
                for (int half = 0; half < 2; half++) {
                    int rowl = wid * 32 + mf * 16 + quad + half * 8;
                    l_s[rowl] = l_s[rowl] * corr_loc[mf][half] +
                                red2[rowl] + red2[64 + rowl] + red2[128 + rowl] + red2[192 + rowl];
                    m_s[rowl] = mn_loc[mf][half];
                }
        }
#pragma unroll
        for (int mf = 0; mf < 2; mf++) {
            float c0 = corr_loc[mf][0], c1 = corr_loc[mf][1];
#pragma unroll
            for (int nf = 0; nf < 8; nf++) {
                oacc[mf][nf][0] *= c0; oacc[mf][nf][1] *= c0;
                oacc[mf][nf][2] *= c1; oacc[mf][nf][3] *= c1;
            }
        }
        CP_WAIT0();
        __syncthreads();   // F

        // ---- O += Ph Vh ----
#pragma unroll
        for (int kk = 0; kk < 4; kk++) {
            const int kb = kk * 8;
            uint32_t pah[2][4];
#pragma unroll
            for (int mf = 0; mf < 2; mf++) {
                uint32_t ar = sb + (uint32_t)(OFF_PH + (wm*32 + mf*16 + a_ro) * AV_STR + kb + a_ko) * 4u;
                LDSM4(pah[mf][0], pah[mf][1], pah[mf][2], pah[mf][3], ar);
            }
#pragma unroll
            for (int g = 0; g < 4; g++) {
                uint32_t br = sb + (uint32_t)(OFF_KV + (wn*64 + (2*g + b_go)*8 + jr) * AV_STR + kb + b_ko) * 4u;
                uint32_t v0h[2], v1h[2];
                LDSM4(v0h[0], v0h[1], v1h[0], v1h[1], br);
#pragma unroll
                for (int mf = 0; mf < 2; mf++) {
                    MMA_F16(oacc[mf][2*g],   pah[mf], v0h);
                    MMA_F16(oacc[mf][2*g+1], pah[mf], v1h);
                }
            }
        }
    }

    // ---- epilogue: write ao as single packed fp16 (Wo GEMM operand) ----
#pragma unroll
    for (int mf = 0; mf < 2; mf++) {
        int r0 = wm * 32 + mf * 16 + quad;
        float i0 = 1.f / l_s[r0], i1 = 1.f / l_s[r0 + 8];
        size_t base0 = ((size_t)(b * T_SEQ + q0 + r0)) * (CDIM / 2) + h * (HD / 2);
        size_t base1 = base0 + 8 * (CDIM / 2);
#pragma unroll
        for (int nf = 0; nf < 8; nf++) {
            int cp_ = wn * 32 + nf * 4 + tq;
            Oh[base0 + cp_] = pack2(to_f16(oacc[mf][nf][0] * i0), to_f16(oacc[mf][nf][1] * i0));
            Oh[base1 + cp_] = pack2(to_f16(oacc[mf][nf][2] * i1), to_f16(oacc[mf][nf][3] * i1));
        }
    }
}

// ---------------- launch ----------------
extern "C" void kernel_launch(void* const* d_in, const int* in_sizes, int n_in,
                              void* d_out, int out_size)
{
    const float* x  = (const float*)d_in[0];
    const float* Wq = (const float*)d_in[1];
    const float* Wk = (const float*)d_in[2];
    const float* Wv = (const float*)d_in[3];
    const float* Wo = (const float*)d_in[4];
    const float* qg = (const float*)d_in[5];
    const float* kg = (const float*)d_in[6];
    float* out = (float*)d_out;

    float *q, *k, *v;
    uint32_t *xh, *aoh, *wqh, *wkh, *wvh, *woh;
    uint32_t *qph, *kph, *vth;
    cudaGetSymbolAddress((void**)&q,   g_q);
    cudaGetSymbolAddress((void**)&k,   g_k);
    cudaGetSymbolAddress((void**)&v,   g_v);
    cudaGetSymbolAddress((void**)&xh,  g_xh);
    cudaGetSymbolAddress((void**)&aoh, g_aoh);
    cudaGetSymbolAddress((void**)&wqh, g_wqh);
    cudaGetSymbolAddress((void**)&wkh, g_wkh);
    cudaGetSymbolAddress((void**)&wvh, g_wvh);
    cudaGetSymbolAddress((void**)&woh, g_woh);
    cudaGetSymbolAddress((void**)&qph, g_qph);
    cudaGetSymbolAddress((void**)&kph, g_kph);
    cudaGetSymbolAddress((void**)&vth, g_vth);

    const int M = BATCH * T_SEQ;   // 8192

    prep_all<<<PREP_BLOCKS, 256>>>(x, Wq, Wk, Wv, Wo, xh, wqh, wkh, wvh, woh);

    cudaFuncSetAttribute(gemm_f16<false>, cudaFuncAttributeMaxDynamicSharedMemorySize, GEMM_SMEM);

    // fused Q+K+V projection (single-term A)
    gemm_f16<false><<<dim3(12, M / 128), 256, GEMM_SMEM>>>(
        M, CDIM, 8, 10, xh, xh,
        wqh, q, CDIM,
        wkh, k, HD,
        wvh, v, HD);

    rmsnorm_rope_fused<<<(M * NH + M) / 8, 256>>>(q, k, qg, kg, qph, kph);

    cudaFuncSetAttribute(transpose_v_f16, cudaFuncAttributeMaxDynamicSharedMemorySize, VT_SMEM);
    transpose_v_f16<<<dim3(T_SEQ / 64, BATCH), 256, VT_SMEM>>>(v, vth);

    cudaFuncSetAttribute(attn_swa_mma, cudaFuncAttributeMaxDynamicSharedMemorySize, ATTN_SMEM);
    attn_swa_mma<<<BATCH * NH * (T_SEQ / 64), 256, ATTN_SMEM>>>(
        qph, kph, vth, aoh);

    // output projection (single-term A: ao hi)
    gemm_f16<false><<<dim3(8, M / 128), 256, GEMM_SMEM>>>(
        M, CDIM, 8, 8, aoh, aoh,
        woh, out, CDIM,
        woh, out, CDIM,
        woh, out, CDIM);
}